// round 9
// baseline (speedup 1.0000x reference)
#include <cuda_runtime.h>
#include <cuda_bf16.h>
#include <cstdint>

#define N_NODES   65536
#define N_EDGES   524288
#define HID       128
#define IN_DIM    64
#define GRAPHS    64
#define NODES_PG  1024
#define LAYERS    3

// weight buffer layout (bf16 hi/lo, [n][k] row-major, k contiguous)
#define OFF_PROJ  0                          // 128 n x 64 k
#define W_TOTAL   (8192 + 6 * 16384)         // 106496
#define OFF_L(l)  (8192 + (2 * (l)) * 16384)
#define OFF_A(l)  (8192 + (2 * (l) + 1) * 16384)

// ---------------- scratch (static device globals: allocation-free) ----------
__device__ float          g_x  [N_NODES * HID];
__device__ __nv_bfloat16  g_xh [N_NODES * HID];
__device__ __nv_bfloat16  g_xl [N_NODES * HID];
__device__ __nv_bfloat16  g_inh[N_NODES * IN_DIM];
__device__ __nv_bfloat16  g_inl[N_NODES * IN_DIM];
__device__ __nv_bfloat16  g_wh [W_TOTAL];
__device__ __nv_bfloat16  g_wl [W_TOTAL];
__device__ float          g_xi [N_NODES * HID];
__device__ float          g_ui [N_NODES * HID];
__device__ float          g_u  [N_NODES * HID];
__device__ float          g_ug [GRAPHS * HID];
__device__ double         g_S1 [2 * HID];
__device__ double         g_S2 [2 * HID];
__device__ float          g_weff[2 * HID * 2];
__device__ float          g_beff[2];
// CSR scratch
__device__ int            g_deg [N_NODES];
__device__ int            g_rows[N_NODES + 1];
__device__ int            g_cur [N_NODES];
__device__ int            g_ssrc[N_EDGES];

// ======================= mma.sync helpers (sm_80+) ===========================
__device__ __forceinline__ uint32_t smem_to_u32(const void* p) {
    uint32_t a;
    asm("{ .reg .u64 t; cvta.to.shared.u64 t, %1; cvt.u32.u64 %0, t; }"
        : "=r"(a) : "l"(p));
    return a;
}
__device__ __forceinline__ void ldmatrix_x4(uint32_t* r, uint32_t addr) {
    asm volatile("ldmatrix.sync.aligned.m8n8.x4.shared.b16 {%0,%1,%2,%3}, [%4];"
                 : "=r"(r[0]), "=r"(r[1]), "=r"(r[2]), "=r"(r[3]) : "r"(addr));
}
__device__ __forceinline__ void mma16816(float* c, const uint32_t* a, const uint32_t* b) {
    asm volatile(
        "mma.sync.aligned.m16n8k16.row.col.f32.bf16.bf16.f32 "
        "{%0,%1,%2,%3}, {%4,%5,%6,%7}, {%8,%9}, {%0,%1,%2,%3};"
        : "+f"(c[0]), "+f"(c[1]), "+f"(c[2]), "+f"(c[3])
        : "r"(a[0]), "r"(a[1]), "r"(a[2]), "r"(a[3]), "r"(b[0]), "r"(b[1]));
}

// SMEM layout for gemm (dynamic). Row stride 144 B: 16B aligned, conflict-free
// for 8-row ldmatrix (rows cover all 32 banks exactly once).
#define PSB      144
#define S_BIAS   0
#define S_AHI    512
#define S_ALO    (S_AHI + 128 * PSB)
#define S_BHI    (S_ALO + 128 * PSB)
#define S_BLO    (S_BHI + 128 * PSB)
#define SMEM_MM  (S_BLO + 128 * PSB)

// ========== GEMM: C[M,128] = act(A[M,K] @ B^T + b), HMMA bf16x2 =============
// A hi/lo bf16 [M,K]; B hi/lo bf16 [128,K] (pre-transposed weights).
// D = Ahi*Bhi + Ahi*Blo + Alo*Bhi, fp32 accum.
// CTA: 128 rows x 128 cols, 256 threads (8 warps, warp = 16 rows x 128 cols).
// Inner loop: B fragments for 8 n-tiles batched via 4 ldmatrix.x4 (hi + lo),
// hoisted ahead of a 24-MMA chain -> LDSM latency overlapped, tensor pipe fed.
__global__ __launch_bounds__(256) void gemm_mma_kernel(
    const __nv_bfloat16* __restrict__ Ahi, const __nv_bfloat16* __restrict__ Alo,
    const __nv_bfloat16* __restrict__ Bhi, const __nv_bfloat16* __restrict__ Blo,
    const float* __restrict__ bias,
    float* __restrict__ C,
    __nv_bfloat16* __restrict__ Chi, __nv_bfloat16* __restrict__ Clo,
    int K, int relu)
{
    extern __shared__ char smem[];
    const uint32_t sb = smem_to_u32(smem);
    const int tid  = threadIdx.x;
    const int wid  = tid >> 5;
    const int lane = tid & 31;
    const int row0 = blockIdx.x * 128;
    const int m0   = wid * 16;
    float* bias_s = (float*)(smem + S_BIAS);
    if (tid < 128) bias_s[tid] = bias[tid];

    float acc[16][4];
#pragma unroll
    for (int nt = 0; nt < 16; nt++) { acc[nt][0]=0.f; acc[nt][1]=0.f; acc[nt][2]=0.f; acc[nt][3]=0.f; }

    const int kq  = K >> 3;          // uint4 per row
    const int nch = K >> 6;          // chunks of 64 k
    for (int kc = 0; kc < nch; kc++) {
        const uint4* AH4 = (const uint4*)Ahi;
        const uint4* AL4 = (const uint4*)Alo;
        const uint4* BH4 = (const uint4*)Bhi;
        const uint4* BL4 = (const uint4*)Blo;
        // A chunk: 128 rows x 64 k, hi+lo (2048 uint4)
#pragma unroll
        for (int it = 0; it < 8; it++) {
            int i  = tid + it * 256;
            int bf = i >> 10;
            int r  = (i >> 3) & 127;
            int c8 = i & 7;
            const uint4* src = bf ? AL4 : AH4;
            uint4 v = src[(size_t)(row0 + r) * kq + kc * 8 + c8];
            *(uint4*)(smem + (bf ? S_ALO : S_AHI) + r * PSB + c8 * 16) = v;
        }
        // B chunk: 128 n-rows x 64 k, hi+lo (2048 uint4)
#pragma unroll
        for (int it = 0; it < 8; it++) {
            int i  = tid + it * 256;
            int bf = i >> 10;
            int r  = (i >> 3) & 127;
            int c8 = i & 7;
            const uint4* src = bf ? BL4 : BH4;
            uint4 v = src[(size_t)r * kq + kc * 8 + c8];
            *(uint4*)(smem + (bf ? S_BLO : S_BHI) + r * PSB + c8 * 16) = v;
        }
        __syncthreads();

#pragma unroll
        for (int ks = 0; ks < 4; ks++) {
            uint32_t ah[4], al[4];
            uint32_t aaddr = sb + S_AHI + (m0 + (lane & 15)) * PSB + ks * 32 + (lane >> 4) * 16;
            ldmatrix_x4(ah, aaddr);
            ldmatrix_x4(al, aaddr + (S_ALO - S_AHI));
#pragma unroll
            for (int h = 0; h < 2; h++) {
                // batched B fragment loads: 8 n-tiles (hi+lo) via 8 ldmatrix.x4
                uint32_t bh[16], bl[16];
#pragma unroll
                for (int p = 0; p < 4; p++) {
                    // x4: lanes 0-7 -> ntile(2p) k0-7, 8-15 -> ntile(2p) k8-15,
                    //     16-23 -> ntile(2p+1) k0-7, 24-31 -> ntile(2p+1) k8-15
                    int nrow = (h * 8 + 2 * p + ((lane >> 4) & 1)) * 8 + (lane & 7);
                    uint32_t baddr = sb + S_BHI + nrow * PSB + ks * 32 + ((lane >> 3) & 1) * 16;
                    ldmatrix_x4(&bh[4 * p], baddr);
                    ldmatrix_x4(&bl[4 * p], baddr + (S_BLO - S_BHI));
                }
                // 24 back-to-back MMAs
#pragma unroll
                for (int q = 0; q < 8; q++) {
                    int nt = h * 8 + q;
                    uint32_t* bhp = &bh[4 * (q >> 1) + 2 * (q & 1)];
                    uint32_t* blp = &bl[4 * (q >> 1) + 2 * (q & 1)];
                    mma16816(acc[nt], ah, bhp);
                    mma16816(acc[nt], ah, blp);
                    mma16816(acc[nt], al, bhp);
                }
            }
        }
        __syncthreads();
    }

    // epilogue: bias(+relu), store fp32 (+ optional bf16 hi/lo split)
    const int group = lane >> 2, tg = lane & 3;
    const int r0 = row0 + m0 + group;
    const int r1 = r0 + 8;
#pragma unroll
    for (int nt = 0; nt < 16; nt++) {
        int col = nt * 8 + tg * 2;
        float b0 = bias_s[col], b1 = bias_s[col + 1];
        float o00 = acc[nt][0] + b0, o01 = acc[nt][1] + b1;
        float o10 = acc[nt][2] + b0, o11 = acc[nt][3] + b1;
        if (relu) {
            o00 = fmaxf(o00, 0.f); o01 = fmaxf(o01, 0.f);
            o10 = fmaxf(o10, 0.f); o11 = fmaxf(o11, 0.f);
        }
        ((float2*)C)[((size_t)r0 * 128 + col) >> 1] = make_float2(o00, o01);
        ((float2*)C)[((size_t)r1 * 128 + col) >> 1] = make_float2(o10, o11);
        if (Chi) {
            __nv_bfloat162 h0, h1, l0, l1;
            h0.x = __float2bfloat16(o00); h0.y = __float2bfloat16(o01);
            h1.x = __float2bfloat16(o10); h1.y = __float2bfloat16(o11);
            l0.x = __float2bfloat16(o00 - __bfloat162float(h0.x));
            l0.y = __float2bfloat16(o01 - __bfloat162float(h0.y));
            l1.x = __float2bfloat16(o10 - __bfloat162float(h1.x));
            l1.y = __float2bfloat16(o11 - __bfloat162float(h1.y));
            size_t i0 = ((size_t)r0 * 128 + col) >> 1;
            size_t i1 = ((size_t)r1 * 128 + col) >> 1;
            ((__nv_bfloat162*)Chi)[i0] = h0;
            ((__nv_bfloat162*)Chi)[i1] = h1;
            ((__nv_bfloat162*)Clo)[i0] = l0;
            ((__nv_bfloat162*)Clo)[i1] = l1;
        }
    }
}

// ---------------- weight pre-conversion: fp32 [K,128] -> bf16 hi/lo [n][k] ---
__global__ void wconv_kernel(const float* __restrict__ Wproj,
                             const float* __restrict__ Wlay,
                             const float* __restrict__ Waggr,
                             __nv_bfloat16* __restrict__ wh,
                             __nv_bfloat16* __restrict__ wl)
{
    int i = blockIdx.x * blockDim.x + threadIdx.x;
    if (i >= W_TOTAL) return;
    float v;
    if (i < 8192) {
        int n = i >> 6, k = i & 63;
        v = Wproj[k * 128 + n];
    } else {
        int j = i - 8192;
        int m = j >> 14;
        int r = j & 16383;
        int n = r >> 7, k = r & 127;
        int l = m >> 1;
        const float* src = (m & 1) ? Waggr : Wlay;
        v = src[(size_t)l * 16384 + k * 128 + n];
    }
    __nv_bfloat16 h = __float2bfloat16(v);
    wh[i] = h;
    wl[i] = __float2bfloat16(v - __bfloat162float(h));
}

// ---------------- split fp32 -> bf16 hi/lo -----------------------------------
__global__ void split_kernel(const float* __restrict__ src,
                             __nv_bfloat16* __restrict__ hi,
                             __nv_bfloat16* __restrict__ lo, int n4)
{
    int i = blockIdx.x * blockDim.x + threadIdx.x;
    if (i >= n4) return;
    float4 v = ((const float4*)src)[i];
    __nv_bfloat162 h0, h1, l0, l1;
    h0.x = __float2bfloat16(v.x); h0.y = __float2bfloat16(v.y);
    h1.x = __float2bfloat16(v.z); h1.y = __float2bfloat16(v.w);
    l0.x = __float2bfloat16(v.x - __bfloat162float(h0.x));
    l0.y = __float2bfloat16(v.y - __bfloat162float(h0.y));
    l1.x = __float2bfloat16(v.z - __bfloat162float(h1.x));
    l1.y = __float2bfloat16(v.w - __bfloat162float(h1.y));
    ((__nv_bfloat162*)hi)[2 * i]     = h0;
    ((__nv_bfloat162*)hi)[2 * i + 1] = h1;
    ((__nv_bfloat162*)lo)[2 * i]     = l0;
    ((__nv_bfloat162*)lo)[2 * i + 1] = l1;
}

// ================= CSR build (once per launch) ===============================
__global__ void zero_int_kernel(int* __restrict__ p, int n)
{
    int i = blockIdx.x * blockDim.x + threadIdx.x;
    if (i < n) p[i] = 0;
}
__global__ void hist_kernel(const int* __restrict__ ei, int* __restrict__ deg, int E)
{
    int i = blockIdx.x * blockDim.x + threadIdx.x;
    if (i < E) atomicAdd(&deg[ei[E + i]], 1);
}
__global__ void scan_kernel(const int* __restrict__ deg, int* __restrict__ rows,
                            int* __restrict__ cur)
{
    __shared__ int part[1024];
    int t = threadIdx.x;
    int base = t * 64;
    int s = 0;
#pragma unroll 8
    for (int i = 0; i < 64; i++) s += deg[base + i];
    part[t] = s;
    __syncthreads();
    for (int off = 1; off < 1024; off <<= 1) {
        int v = (t >= off) ? part[t - off] : 0;
        __syncthreads();
        part[t] += v;
        __syncthreads();
    }
    int run = part[t] - s;
    for (int i = 0; i < 64; i++) {
        rows[base + i] = run;
        cur[base + i]  = run;
        run += deg[base + i];
    }
    if (t == 1023) rows[N_NODES] = part[1023];
}
__global__ void fill_kernel(const int* __restrict__ ei, int* __restrict__ cur,
                            int* __restrict__ ssrc, int E)
{
    int e = blockIdx.x * blockDim.x + threadIdx.x;
    if (e >= E) return;
    int d = ei[E + e];
    int p = atomicAdd(&cur[d], 1);
    ssrc[p] = ei[e];
}

// ---- fused: u[n] = sum ui[src]; x = relu(xi + u); emit x fp32 + bf16 hi/lo --
__global__ __launch_bounds__(256) void agg_fuse_kernel(
    const float* __restrict__ ui, const int* __restrict__ rows,
    const int* __restrict__ ssrc, const float* __restrict__ xi,
    float* __restrict__ u, float* __restrict__ x,
    __nv_bfloat16* __restrict__ xh, __nv_bfloat16* __restrict__ xl)
{
    int w    = blockIdx.x * 8 + (threadIdx.x >> 5);
    int lane = threadIdx.x & 31;
    int st = rows[w], en = rows[w + 1];
    float4 a = make_float4(0.f, 0.f, 0.f, 0.f);
    float4 b = make_float4(0.f, 0.f, 0.f, 0.f);
    const float4* ui4 = (const float4*)ui;
    int e = st;
    for (; e + 1 < en; e += 2) {
        int s0 = __ldg(&ssrc[e]);
        int s1 = __ldg(&ssrc[e + 1]);
        float4 v0 = __ldg(&ui4[(size_t)s0 * 32 + lane]);
        float4 v1 = __ldg(&ui4[(size_t)s1 * 32 + lane]);
        a.x += v0.x; a.y += v0.y; a.z += v0.z; a.w += v0.w;
        b.x += v1.x; b.y += v1.y; b.z += v1.z; b.w += v1.w;
    }
    if (e < en) {
        int s0 = __ldg(&ssrc[e]);
        float4 v0 = __ldg(&ui4[(size_t)s0 * 32 + lane]);
        a.x += v0.x; a.y += v0.y; a.z += v0.z; a.w += v0.w;
    }
    a.x += b.x; a.y += b.y; a.z += b.z; a.w += b.w;
    size_t idx = (size_t)w * 32 + lane;
    ((float4*)u)[idx] = a;
    float4 t = ((const float4*)xi)[idx];
    float4 o;
    o.x = fmaxf(t.x + a.x, 0.f);
    o.y = fmaxf(t.y + a.y, 0.f);
    o.z = fmaxf(t.z + a.z, 0.f);
    o.w = fmaxf(t.w + a.w, 0.f);
    ((float4*)x)[idx] = o;
    __nv_bfloat162 h0, h1, l0, l1;
    h0.x = __float2bfloat16(o.x); h0.y = __float2bfloat16(o.y);
    h1.x = __float2bfloat16(o.z); h1.y = __float2bfloat16(o.w);
    l0.x = __float2bfloat16(o.x - __bfloat162float(h0.x));
    l0.y = __float2bfloat16(o.y - __bfloat162float(h0.y));
    l1.x = __float2bfloat16(o.z - __bfloat162float(h1.x));
    l1.y = __float2bfloat16(o.w - __bfloat162float(h1.y));
    ((__nv_bfloat162*)xh)[2 * idx]     = h0;
    ((__nv_bfloat162*)xh)[2 * idx + 1] = h1;
    ((__nv_bfloat162*)xl)[2 * idx]     = l0;
    ((__nv_bfloat162*)xl)[2 * idx + 1] = l1;
}

// ---------------- per-graph sum of u -----------------------------------------
__global__ void graph_reduce_kernel(const float* __restrict__ u,
                                    float* __restrict__ ug)
{
    int g = blockIdx.x;
    int c = threadIdx.x;
    const float* base = u + (size_t)g * NODES_PG * HID + c;
    float s = 0.f;
#pragma unroll 8
    for (int r = 0; r < NODES_PG; r++) s += base[(size_t)r * HID];
    ug[g * HID + c] = s;
}

// ---------------- column stats -----------------------------------------------
__global__ void zero_stats_kernel(double* __restrict__ s1, double* __restrict__ s2)
{
    int i = threadIdx.x;
    s1[i] = 0.0; s2[i] = 0.0;
}
__global__ void xstats_kernel(const float* __restrict__ x,
                              double* __restrict__ S1, double* __restrict__ S2)
{
    int c = threadIdx.x;
    int b = blockIdx.x;
    const float* base = x + (size_t)b * 128 * HID + c;
    float s1 = 0.f, s2 = 0.f;
#pragma unroll 8
    for (int r = 0; r < 128; r++) {
        float v = base[(size_t)r * HID];
        s1 += v; s2 += v * v;
    }
    atomicAdd(&S1[c], (double)s1);
    atomicAdd(&S2[c], (double)s2);
}
__global__ void ugstats_kernel(const float* __restrict__ ug,
                               double* __restrict__ S1, double* __restrict__ S2)
{
    int c = threadIdx.x;
    double s1 = 0.0, s2 = 0.0;
    for (int g = 0; g < GRAPHS; g++) {
        double v = (double)ug[g * HID + c];
        s1 += v; s2 += v * v;
    }
    S1[HID + c] = s1;
    S2[HID + c] = s2;
}

// ---------------- fold BN into final linear ----------------------------------
__global__ void prep_kernel(const double* __restrict__ S1, const double* __restrict__ S2,
                            const float* __restrict__ gamma, const float* __restrict__ beta,
                            const float* __restrict__ Wf, const float* __restrict__ bf,
                            float* __restrict__ weff, float* __restrict__ beff)
{
    __shared__ float r0[256], r1[256];
    int c = threadIdx.x;
    double div  = (c < HID) ? (double)N_NODES : (double)GRAPHS;
    double mean = S1[c] / div;
    double var  = S2[c] / div - mean * mean;
    float  s     = gamma[c] * rsqrtf((float)var + 1e-5f);
    float  shift = beta[c] - (float)mean * s;
    float  w0 = Wf[c * 2 + 0], w1 = Wf[c * 2 + 1];
    weff[c * 2 + 0] = s * w0;
    weff[c * 2 + 1] = s * w1;
    r0[c] = shift * w0;
    r1[c] = shift * w1;
    __syncthreads();
    for (int st = 128; st > 0; st >>= 1) {
        if (c < st) { r0[c] += r0[c + st]; r1[c] += r1[c + st]; }
        __syncthreads();
    }
    if (c == 0) { beff[0] = bf[0] + r0[0]; beff[1] = bf[1] + r1[0]; }
}

// ---------------- final: out[n] = [x_n | ug_g] @ Weff + beff -----------------
__global__ __launch_bounds__(256) void final_kernel(
    const float* __restrict__ x, const float* __restrict__ ug,
    const float* __restrict__ weff, const float* __restrict__ beff,
    float* __restrict__ out)
{
    __shared__ float wsh[512];
    __shared__ float ush[HID];
    __shared__ float bsh[2];
    int tid = threadIdx.x;
    int n0  = blockIdx.x * 256;
    wsh[tid]       = weff[tid];
    wsh[tid + 256] = weff[tid + 256];
    if (tid < 2)   bsh[tid] = beff[tid];
    int g = n0 >> 10;
    if (tid < HID) ush[tid] = ug[g * HID + tid];
    __syncthreads();

    int n = n0 + tid;
    float a0 = bsh[0], a1 = bsh[1];
    const float4* xr = (const float4*)(x + (size_t)n * HID);
#pragma unroll
    for (int c4 = 0; c4 < 32; c4++) {
        float4 v = xr[c4];
        int c = c4 * 4;
        a0 += v.x * wsh[2*c+0] + v.y * wsh[2*c+2] + v.z * wsh[2*c+4] + v.w * wsh[2*c+6];
        a1 += v.x * wsh[2*c+1] + v.y * wsh[2*c+3] + v.z * wsh[2*c+5] + v.w * wsh[2*c+7];
    }
#pragma unroll 8
    for (int c = 0; c < HID; c++) {
        float uv = ush[c];
        a0 += uv * wsh[2 * (HID + c) + 0];
        a1 += uv * wsh[2 * (HID + c) + 1];
    }
    out[n * 2 + 0] = a0;
    out[n * 2 + 1] = a1;
}

// ---------------- host orchestration ----------------------------------------
extern "C" void kernel_launch(void* const* d_in, const int* in_sizes, int n_in,
                              void* d_out, int out_size)
{
    const float* x_in    = (const float*)d_in[0];
    const int*   ei      = (const int*)  d_in[1];
    const float* W_proj  = (const float*)d_in[3];
    const float* b_proj  = (const float*)d_in[4];
    const float* W_lay   = (const float*)d_in[5];
    const float* b_lay   = (const float*)d_in[6];
    const float* W_aggr  = (const float*)d_in[7];
    const float* b_aggr  = (const float*)d_in[8];
    const float* gamma   = (const float*)d_in[9];
    const float* beta    = (const float*)d_in[10];
    const float* W_final = (const float*)d_in[11];
    const float* b_final = (const float*)d_in[12];
    float* out = (float*)d_out;

    const int M = in_sizes[0] / IN_DIM;     // 65536
    const int E = in_sizes[1] / 2;          // 524288

    float *px, *pxi, *pui, *pu, *pug, *pweff, *pbeff;
    __nv_bfloat16 *pxh, *pxl, *pinh, *pinl, *pwh, *pwl;
    double *ps1, *ps2;
    int *pdeg, *prows, *pcur, *pssrc;
    cudaGetSymbolAddress((void**)&px,    g_x);
    cudaGetSymbolAddress((void**)&pxh,   g_xh);
    cudaGetSymbolAddress((void**)&pxl,   g_xl);
    cudaGetSymbolAddress((void**)&pinh,  g_inh);
    cudaGetSymbolAddress((void**)&pinl,  g_inl);
    cudaGetSymbolAddress((void**)&pwh,   g_wh);
    cudaGetSymbolAddress((void**)&pwl,   g_wl);
    cudaGetSymbolAddress((void**)&pxi,   g_xi);
    cudaGetSymbolAddress((void**)&pui,   g_ui);
    cudaGetSymbolAddress((void**)&pu,    g_u);
    cudaGetSymbolAddress((void**)&pug,   g_ug);
    cudaGetSymbolAddress((void**)&ps1,   g_S1);
    cudaGetSymbolAddress((void**)&ps2,   g_S2);
    cudaGetSymbolAddress((void**)&pweff, g_weff);
    cudaGetSymbolAddress((void**)&pbeff, g_beff);
    cudaGetSymbolAddress((void**)&pdeg,  g_deg);
    cudaGetSymbolAddress((void**)&prows, g_rows);
    cudaGetSymbolAddress((void**)&pcur,  g_cur);
    cudaGetSymbolAddress((void**)&pssrc, g_ssrc);

    cudaFuncSetAttribute(gemm_mma_kernel,
                         cudaFuncAttributeMaxDynamicSharedMemorySize, SMEM_MM);

    const int M4 = M * HID / 4;
    const int gblk = M / 128;               // 512

    // 1: weight pre-conversion   2: input split   3: CSR zero
    wconv_kernel<<<(W_TOTAL + 255) / 256, 256>>>(W_proj, W_lay, W_aggr, pwh, pwl);
    split_kernel<<<(M * IN_DIM / 4 + 255) / 256, 256>>>(x_in, pinh, pinl, M * IN_DIM / 4);
    zero_int_kernel<<<(M + 1023) / 1024, 1024>>>(pdeg, M);
    // 4: projection GEMM  (the launch ncu captures)
    gemm_mma_kernel<<<gblk, 256, SMEM_MM>>>(pinh, pinl, pwh + OFF_PROJ, pwl + OFF_PROJ,
                                            b_proj, px, pxh, pxl, IN_DIM, 1);
    // CSR build continues
    hist_kernel<<<(E + 255) / 256, 256>>>(ei, pdeg, E);
    scan_kernel<<<1, 1024>>>(pdeg, prows, pcur);
    fill_kernel<<<(E + 255) / 256, 256>>>(ei, pcur, pssrc, E);

    for (int l = 0; l < LAYERS; l++) {
        gemm_mma_kernel<<<gblk, 256, SMEM_MM>>>(pxh, pxl, pwh + OFF_L(l), pwl + OFF_L(l),
                                                b_lay + l * HID, pxi, nullptr, nullptr, HID, 0);
        gemm_mma_kernel<<<gblk, 256, SMEM_MM>>>(pxh, pxl, pwh + OFF_A(l), pwl + OFF_A(l),
                                                b_aggr + l * HID, pui, nullptr, nullptr, HID, 0);
        agg_fuse_kernel<<<M / 8, 256>>>(pui, prows, pssrc, pxi, pu, px, pxh, pxl);
    }

    graph_reduce_kernel<<<GRAPHS, HID>>>(pu, pug);
    zero_stats_kernel<<<1, 256>>>(ps1, ps2);
    xstats_kernel<<<M / 128, HID>>>(px, ps1, ps2);
    ugstats_kernel<<<1, HID>>>(pug, ps1, ps2);
    prep_kernel<<<1, 256>>>(ps1, ps2, gamma, beta, W_final, b_final, pweff, pbeff);
    final_kernel<<<M / 256, 256>>>(px, pug, pweff, pbeff, out);

    (void)n_in; (void)out_size;
    (void)M4;
}

// round 10
// speedup vs baseline: 1.0798x; 1.0798x over previous
#include <cuda_runtime.h>
#include <cuda_bf16.h>
#include <cstdint>

#define N_NODES   65536
#define N_EDGES   524288
#define HID       128
#define IN_DIM    64
#define GRAPHS    64
#define NODES_PG  1024
#define LAYERS    3

// weight buffer layout (bf16 hi/lo, [n][k] row-major, k contiguous)
#define OFF_PROJ  0                          // 128 n x 64 k
#define W_TOTAL   (8192 + 6 * 16384)         // 106496
#define OFF_L(l)  (8192 + (2 * (l)) * 16384)
#define OFF_A(l)  (8192 + (2 * (l) + 1) * 16384)

// ---------------- scratch (static device globals: allocation-free) ----------
__device__ float          g_x  [N_NODES * HID];
__device__ __nv_bfloat16  g_xh [N_NODES * HID];
__device__ __nv_bfloat16  g_xl [N_NODES * HID];
__device__ __nv_bfloat16  g_inh[N_NODES * IN_DIM];
__device__ __nv_bfloat16  g_inl[N_NODES * IN_DIM];
__device__ __nv_bfloat16  g_wh [W_TOTAL];
__device__ __nv_bfloat16  g_wl [W_TOTAL];
__device__ float          g_xi [N_NODES * HID];
__device__ float          g_ui [N_NODES * HID];
__device__ float          g_u  [N_NODES * HID];
__device__ float          g_ug [GRAPHS * HID];
__device__ double         g_S1 [2 * HID];
__device__ double         g_S2 [2 * HID];
__device__ float          g_weff[2 * HID * 2];
__device__ float          g_beff[2];
// CSR scratch
__device__ int            g_deg [N_NODES];
__device__ int            g_rows[N_NODES + 1];
__device__ int            g_cur [N_NODES];
__device__ int            g_ssrc[N_EDGES];

// ======================= mma.sync helpers (sm_80+) ===========================
__device__ __forceinline__ uint32_t smem_to_u32(const void* p) {
    uint32_t a;
    asm("{ .reg .u64 t; cvta.to.shared.u64 t, %1; cvt.u32.u64 %0, t; }"
        : "=r"(a) : "l"(p));
    return a;
}
__device__ __forceinline__ void ldmatrix_x4(uint32_t* r, uint32_t addr) {
    asm volatile("ldmatrix.sync.aligned.m8n8.x4.shared.b16 {%0,%1,%2,%3}, [%4];"
                 : "=r"(r[0]), "=r"(r[1]), "=r"(r[2]), "=r"(r[3]) : "r"(addr));
}
__device__ __forceinline__ void mma16816(float* c, const uint32_t* a, const uint32_t* b) {
    asm volatile(
        "mma.sync.aligned.m16n8k16.row.col.f32.bf16.bf16.f32 "
        "{%0,%1,%2,%3}, {%4,%5,%6,%7}, {%8,%9}, {%0,%1,%2,%3};"
        : "+f"(c[0]), "+f"(c[1]), "+f"(c[2]), "+f"(c[3])
        : "r"(a[0]), "r"(a[1]), "r"(a[2]), "r"(a[3]), "r"(b[0]), "r"(b[1]));
}

// SMEM layout for gemm (dynamic). Row stride 144 B: 16B aligned, conflict-free
// for 8-row ldmatrix (rows cover all 32 banks exactly once).
#define PSB      144
#define S_BIAS   0
#define S_AHI    512
#define S_ALO    (S_AHI + 128 * PSB)
#define S_BHI    (S_ALO + 128 * PSB)
#define S_BLO    (S_BHI + 128 * PSB)
#define SMEM_MM  (S_BLO + 128 * PSB)

// ========== GEMM: C[M,128] = act(A[M,K] @ B^T + b), HMMA bf16x2 =============
// A hi/lo bf16 [M,K]; B hi/lo bf16 [128,K] (pre-transposed weights).
// D = Ahi*Bhi + Ahi*Blo + Alo*Bhi, fp32 accum.
// CTA: 128 rows x 128 cols, 256 threads (8 warps, warp = 16 rows x 128 cols).
// Inner loop: B fragments loaded pair-wise (2 n-tiles per ldmatrix.x4) with a
// one-pair lookahead double buffer -> LDSM latency overlapped with a 6-MMA
// chain.  __launch_bounds__(256,2) pins regs <= 128 so 2 CTAs/SM are resident.
__global__ __launch_bounds__(256, 2) void gemm_mma_kernel(
    const __nv_bfloat16* __restrict__ Ahi, const __nv_bfloat16* __restrict__ Alo,
    const __nv_bfloat16* __restrict__ Bhi, const __nv_bfloat16* __restrict__ Blo,
    const float* __restrict__ bias,
    float* __restrict__ C,
    __nv_bfloat16* __restrict__ Chi, __nv_bfloat16* __restrict__ Clo,
    int K, int relu)
{
    extern __shared__ char smem[];
    const uint32_t sb = smem_to_u32(smem);
    const int tid  = threadIdx.x;
    const int wid  = tid >> 5;
    const int lane = tid & 31;
    const int row0 = blockIdx.x * 128;
    const int m0   = wid * 16;
    float* bias_s = (float*)(smem + S_BIAS);
    if (tid < 128) bias_s[tid] = bias[tid];

    float acc[16][4];
#pragma unroll
    for (int nt = 0; nt < 16; nt++) { acc[nt][0]=0.f; acc[nt][1]=0.f; acc[nt][2]=0.f; acc[nt][3]=0.f; }

    const int kq  = K >> 3;          // uint4 per row
    const int nch = K >> 6;          // chunks of 64 k
    for (int kc = 0; kc < nch; kc++) {
        const uint4* AH4 = (const uint4*)Ahi;
        const uint4* AL4 = (const uint4*)Alo;
        const uint4* BH4 = (const uint4*)Bhi;
        const uint4* BL4 = (const uint4*)Blo;
        // A chunk: 128 rows x 64 k, hi+lo (2048 uint4)
#pragma unroll
        for (int it = 0; it < 8; it++) {
            int i  = tid + it * 256;
            int bf = i >> 10;
            int r  = (i >> 3) & 127;
            int c8 = i & 7;
            const uint4* src = bf ? AL4 : AH4;
            uint4 v = src[(size_t)(row0 + r) * kq + kc * 8 + c8];
            *(uint4*)(smem + (bf ? S_ALO : S_AHI) + r * PSB + c8 * 16) = v;
        }
        // B chunk: 128 n-rows x 64 k, hi+lo (2048 uint4)
#pragma unroll
        for (int it = 0; it < 8; it++) {
            int i  = tid + it * 256;
            int bf = i >> 10;
            int r  = (i >> 3) & 127;
            int c8 = i & 7;
            const uint4* src = bf ? BL4 : BH4;
            uint4 v = src[(size_t)r * kq + kc * 8 + c8];
            *(uint4*)(smem + (bf ? S_BLO : S_BHI) + r * PSB + c8 * 16) = v;
        }
        __syncthreads();

#pragma unroll
        for (int ks = 0; ks < 4; ks++) {
            uint32_t ah[4], al[4];
            uint32_t aaddr = sb + S_AHI + (m0 + (lane & 15)) * PSB + ks * 32 + (lane >> 4) * 16;
            ldmatrix_x4(ah, aaddr);
            ldmatrix_x4(al, aaddr + (S_ALO - S_AHI));

            // B pair p covers n-tiles (2p, 2p+1): one x4 ldmatrix per half.
            // lanes 0-7 -> nt(2p) k0-7, 8-15 -> nt(2p) k8-15,
            // 16-23 -> nt(2p+1) k0-7, 24-31 -> nt(2p+1) k8-15.
            uint32_t bh[2][4], bl[2][4];
            const uint32_t bbase = sb + S_BHI + (((lane >> 4) & 1) * 8 + (lane & 7)) * PSB
                                 + ks * 32 + ((lane >> 3) & 1) * 16;
            ldmatrix_x4(bh[0], bbase);
            ldmatrix_x4(bl[0], bbase + (S_BLO - S_BHI));
#pragma unroll
            for (int p = 0; p < 8; p++) {
                const int cur = p & 1, nxt = cur ^ 1;
                if (p < 7) {
                    uint32_t nb = bbase + (p + 1) * (16 * PSB);
                    ldmatrix_x4(bh[nxt], nb);
                    ldmatrix_x4(bl[nxt], nb + (S_BLO - S_BHI));
                }
                const int nt0 = 2 * p, nt1 = 2 * p + 1;
                mma16816(acc[nt0], ah, &bh[cur][0]);
                mma16816(acc[nt0], ah, &bl[cur][0]);
                mma16816(acc[nt0], al, &bh[cur][0]);
                mma16816(acc[nt1], ah, &bh[cur][2]);
                mma16816(acc[nt1], ah, &bl[cur][2]);
                mma16816(acc[nt1], al, &bh[cur][2]);
            }
        }
        __syncthreads();
    }

    // epilogue: bias(+relu), store fp32 (+ optional bf16 hi/lo split)
    const int group = lane >> 2, tg = lane & 3;
    const int r0 = row0 + m0 + group;
    const int r1 = r0 + 8;
#pragma unroll
    for (int nt = 0; nt < 16; nt++) {
        int col = nt * 8 + tg * 2;
        float b0 = bias_s[col], b1 = bias_s[col + 1];
        float o00 = acc[nt][0] + b0, o01 = acc[nt][1] + b1;
        float o10 = acc[nt][2] + b0, o11 = acc[nt][3] + b1;
        if (relu) {
            o00 = fmaxf(o00, 0.f); o01 = fmaxf(o01, 0.f);
            o10 = fmaxf(o10, 0.f); o11 = fmaxf(o11, 0.f);
        }
        ((float2*)C)[((size_t)r0 * 128 + col) >> 1] = make_float2(o00, o01);
        ((float2*)C)[((size_t)r1 * 128 + col) >> 1] = make_float2(o10, o11);
        if (Chi) {
            __nv_bfloat162 h0, h1, l0, l1;
            h0.x = __float2bfloat16(o00); h0.y = __float2bfloat16(o01);
            h1.x = __float2bfloat16(o10); h1.y = __float2bfloat16(o11);
            l0.x = __float2bfloat16(o00 - __bfloat162float(h0.x));
            l0.y = __float2bfloat16(o01 - __bfloat162float(h0.y));
            l1.x = __float2bfloat16(o10 - __bfloat162float(h1.x));
            l1.y = __float2bfloat16(o11 - __bfloat162float(h1.y));
            size_t i0 = ((size_t)r0 * 128 + col) >> 1;
            size_t i1 = ((size_t)r1 * 128 + col) >> 1;
            ((__nv_bfloat162*)Chi)[i0] = h0;
            ((__nv_bfloat162*)Chi)[i1] = h1;
            ((__nv_bfloat162*)Clo)[i0] = l0;
            ((__nv_bfloat162*)Clo)[i1] = l1;
        }
    }
}

// ---------------- weight pre-conversion: fp32 [K,128] -> bf16 hi/lo [n][k] ---
__global__ void wconv_kernel(const float* __restrict__ Wproj,
                             const float* __restrict__ Wlay,
                             const float* __restrict__ Waggr,
                             __nv_bfloat16* __restrict__ wh,
                             __nv_bfloat16* __restrict__ wl)
{
    int i = blockIdx.x * blockDim.x + threadIdx.x;
    if (i >= W_TOTAL) return;
    float v;
    if (i < 8192) {
        int n = i >> 6, k = i & 63;
        v = Wproj[k * 128 + n];
    } else {
        int j = i - 8192;
        int m = j >> 14;
        int r = j & 16383;
        int n = r >> 7, k = r & 127;
        int l = m >> 1;
        const float* src = (m & 1) ? Waggr : Wlay;
        v = src[(size_t)l * 16384 + k * 128 + n];
    }
    __nv_bfloat16 h = __float2bfloat16(v);
    wh[i] = h;
    wl[i] = __float2bfloat16(v - __bfloat162float(h));
}

// ---------------- split fp32 -> bf16 hi/lo -----------------------------------
__global__ void split_kernel(const float* __restrict__ src,
                             __nv_bfloat16* __restrict__ hi,
                             __nv_bfloat16* __restrict__ lo, int n4)
{
    int i = blockIdx.x * blockDim.x + threadIdx.x;
    if (i >= n4) return;
    float4 v = ((const float4*)src)[i];
    __nv_bfloat162 h0, h1, l0, l1;
    h0.x = __float2bfloat16(v.x); h0.y = __float2bfloat16(v.y);
    h1.x = __float2bfloat16(v.z); h1.y = __float2bfloat16(v.w);
    l0.x = __float2bfloat16(v.x - __bfloat162float(h0.x));
    l0.y = __float2bfloat16(v.y - __bfloat162float(h0.y));
    l1.x = __float2bfloat16(v.z - __bfloat162float(h1.x));
    l1.y = __float2bfloat16(v.w - __bfloat162float(h1.y));
    ((__nv_bfloat162*)hi)[2 * i]     = h0;
    ((__nv_bfloat162*)hi)[2 * i + 1] = h1;
    ((__nv_bfloat162*)lo)[2 * i]     = l0;
    ((__nv_bfloat162*)lo)[2 * i + 1] = l1;
}

// ================= CSR build (once per launch) ===============================
__global__ void zero_int_kernel(int* __restrict__ p, int n)
{
    int i = blockIdx.x * blockDim.x + threadIdx.x;
    if (i < n) p[i] = 0;
}
__global__ void hist_kernel(const int* __restrict__ ei, int* __restrict__ deg, int E)
{
    int i = blockIdx.x * blockDim.x + threadIdx.x;
    if (i < E) atomicAdd(&deg[ei[E + i]], 1);
}
__global__ void scan_kernel(const int* __restrict__ deg, int* __restrict__ rows,
                            int* __restrict__ cur)
{
    __shared__ int part[1024];
    int t = threadIdx.x;
    int base = t * 64;
    int s = 0;
#pragma unroll 8
    for (int i = 0; i < 64; i++) s += deg[base + i];
    part[t] = s;
    __syncthreads();
    for (int off = 1; off < 1024; off <<= 1) {
        int v = (t >= off) ? part[t - off] : 0;
        __syncthreads();
        part[t] += v;
        __syncthreads();
    }
    int run = part[t] - s;
    for (int i = 0; i < 64; i++) {
        rows[base + i] = run;
        cur[base + i]  = run;
        run += deg[base + i];
    }
    if (t == 1023) rows[N_NODES] = part[1023];
}
__global__ void fill_kernel(const int* __restrict__ ei, int* __restrict__ cur,
                            int* __restrict__ ssrc, int E)
{
    int e = blockIdx.x * blockDim.x + threadIdx.x;
    if (e >= E) return;
    int d = ei[E + e];
    int p = atomicAdd(&cur[d], 1);
    ssrc[p] = ei[e];
}

// ---- fused: u[n] = sum ui[src]; x = relu(xi + u); emit x fp32 + bf16 hi/lo --
__global__ __launch_bounds__(256) void agg_fuse_kernel(
    const float* __restrict__ ui, const int* __restrict__ rows,
    const int* __restrict__ ssrc, const float* __restrict__ xi,
    float* __restrict__ u, float* __restrict__ x,
    __nv_bfloat16* __restrict__ xh, __nv_bfloat16* __restrict__ xl)
{
    int w    = blockIdx.x * 8 + (threadIdx.x >> 5);
    int lane = threadIdx.x & 31;
    int st = rows[w], en = rows[w + 1];
    float4 a = make_float4(0.f, 0.f, 0.f, 0.f);
    float4 b = make_float4(0.f, 0.f, 0.f, 0.f);
    const float4* ui4 = (const float4*)ui;
    int e = st;
    for (; e + 1 < en; e += 2) {
        int s0 = __ldg(&ssrc[e]);
        int s1 = __ldg(&ssrc[e + 1]);
        float4 v0 = __ldg(&ui4[(size_t)s0 * 32 + lane]);
        float4 v1 = __ldg(&ui4[(size_t)s1 * 32 + lane]);
        a.x += v0.x; a.y += v0.y; a.z += v0.z; a.w += v0.w;
        b.x += v1.x; b.y += v1.y; b.z += v1.z; b.w += v1.w;
    }
    if (e < en) {
        int s0 = __ldg(&ssrc[e]);
        float4 v0 = __ldg(&ui4[(size_t)s0 * 32 + lane]);
        a.x += v0.x; a.y += v0.y; a.z += v0.z; a.w += v0.w;
    }
    a.x += b.x; a.y += b.y; a.z += b.z; a.w += b.w;
    size_t idx = (size_t)w * 32 + lane;
    ((float4*)u)[idx] = a;
    float4 t = ((const float4*)xi)[idx];
    float4 o;
    o.x = fmaxf(t.x + a.x, 0.f);
    o.y = fmaxf(t.y + a.y, 0.f);
    o.z = fmaxf(t.z + a.z, 0.f);
    o.w = fmaxf(t.w + a.w, 0.f);
    ((float4*)x)[idx] = o;
    __nv_bfloat162 h0, h1, l0, l1;
    h0.x = __float2bfloat16(o.x); h0.y = __float2bfloat16(o.y);
    h1.x = __float2bfloat16(o.z); h1.y = __float2bfloat16(o.w);
    l0.x = __float2bfloat16(o.x - __bfloat162float(h0.x));
    l0.y = __float2bfloat16(o.y - __bfloat162float(h0.y));
    l1.x = __float2bfloat16(o.z - __bfloat162float(h1.x));
    l1.y = __float2bfloat16(o.w - __bfloat162float(h1.y));
    ((__nv_bfloat162*)xh)[2 * idx]     = h0;
    ((__nv_bfloat162*)xh)[2 * idx + 1] = h1;
    ((__nv_bfloat162*)xl)[2 * idx]     = l0;
    ((__nv_bfloat162*)xl)[2 * idx + 1] = l1;
}

// ---------------- per-graph sum of u -----------------------------------------
__global__ void graph_reduce_kernel(const float* __restrict__ u,
                                    float* __restrict__ ug)
{
    int g = blockIdx.x;
    int c = threadIdx.x;
    const float* base = u + (size_t)g * NODES_PG * HID + c;
    float s = 0.f;
#pragma unroll 8
    for (int r = 0; r < NODES_PG; r++) s += base[(size_t)r * HID];
    ug[g * HID + c] = s;
}

// ---------------- column stats -----------------------------------------------
__global__ void zero_stats_kernel(double* __restrict__ s1, double* __restrict__ s2)
{
    int i = threadIdx.x;
    s1[i] = 0.0; s2[i] = 0.0;
}
__global__ void xstats_kernel(const float* __restrict__ x,
                              double* __restrict__ S1, double* __restrict__ S2)
{
    int c = threadIdx.x;
    int b = blockIdx.x;
    const float* base = x + (size_t)b * 128 * HID + c;
    float s1 = 0.f, s2 = 0.f;
#pragma unroll 8
    for (int r = 0; r < 128; r++) {
        float v = base[(size_t)r * HID];
        s1 += v; s2 += v * v;
    }
    atomicAdd(&S1[c], (double)s1);
    atomicAdd(&S2[c], (double)s2);
}
__global__ void ugstats_kernel(const float* __restrict__ ug,
                               double* __restrict__ S1, double* __restrict__ S2)
{
    int c = threadIdx.x;
    double s1 = 0.0, s2 = 0.0;
    for (int g = 0; g < GRAPHS; g++) {
        double v = (double)ug[g * HID + c];
        s1 += v; s2 += v * v;
    }
    S1[HID + c] = s1;
    S2[HID + c] = s2;
}

// ---------------- fold BN into final linear ----------------------------------
__global__ void prep_kernel(const double* __restrict__ S1, const double* __restrict__ S2,
                            const float* __restrict__ gamma, const float* __restrict__ beta,
                            const float* __restrict__ Wf, const float* __restrict__ bf,
                            float* __restrict__ weff, float* __restrict__ beff)
{
    __shared__ float r0[256], r1[256];
    int c = threadIdx.x;
    double div  = (c < HID) ? (double)N_NODES : (double)GRAPHS;
    double mean = S1[c] / div;
    double var  = S2[c] / div - mean * mean;
    float  s     = gamma[c] * rsqrtf((float)var + 1e-5f);
    float  shift = beta[c] - (float)mean * s;
    float  w0 = Wf[c * 2 + 0], w1 = Wf[c * 2 + 1];
    weff[c * 2 + 0] = s * w0;
    weff[c * 2 + 1] = s * w1;
    r0[c] = shift * w0;
    r1[c] = shift * w1;
    __syncthreads();
    for (int st = 128; st > 0; st >>= 1) {
        if (c < st) { r0[c] += r0[c + st]; r1[c] += r1[c + st]; }
        __syncthreads();
    }
    if (c == 0) { beff[0] = bf[0] + r0[0]; beff[1] = bf[1] + r1[0]; }
}

// ---------------- final: out[n] = [x_n | ug_g] @ Weff + beff -----------------
__global__ __launch_bounds__(256) void final_kernel(
    const float* __restrict__ x, const float* __restrict__ ug,
    const float* __restrict__ weff, const float* __restrict__ beff,
    float* __restrict__ out)
{
    __shared__ float wsh[512];
    __shared__ float ush[HID];
    __shared__ float bsh[2];
    int tid = threadIdx.x;
    int n0  = blockIdx.x * 256;
    wsh[tid]       = weff[tid];
    wsh[tid + 256] = weff[tid + 256];
    if (tid < 2)   bsh[tid] = beff[tid];
    int g = n0 >> 10;
    if (tid < HID) ush[tid] = ug[g * HID + tid];
    __syncthreads();

    int n = n0 + tid;
    float a0 = bsh[0], a1 = bsh[1];
    const float4* xr = (const float4*)(x + (size_t)n * HID);
#pragma unroll
    for (int c4 = 0; c4 < 32; c4++) {
        float4 v = xr[c4];
        int c = c4 * 4;
        a0 += v.x * wsh[2*c+0] + v.y * wsh[2*c+2] + v.z * wsh[2*c+4] + v.w * wsh[2*c+6];
        a1 += v.x * wsh[2*c+1] + v.y * wsh[2*c+3] + v.z * wsh[2*c+5] + v.w * wsh[2*c+7];
    }
#pragma unroll 8
    for (int c = 0; c < HID; c++) {
        float uv = ush[c];
        a0 += uv * wsh[2 * (HID + c) + 0];
        a1 += uv * wsh[2 * (HID + c) + 1];
    }
    out[n * 2 + 0] = a0;
    out[n * 2 + 1] = a1;
}

// ---------------- host orchestration ----------------------------------------
extern "C" void kernel_launch(void* const* d_in, const int* in_sizes, int n_in,
                              void* d_out, int out_size)
{
    const float* x_in    = (const float*)d_in[0];
    const int*   ei      = (const int*)  d_in[1];
    const float* W_proj  = (const float*)d_in[3];
    const float* b_proj  = (const float*)d_in[4];
    const float* W_lay   = (const float*)d_in[5];
    const float* b_lay   = (const float*)d_in[6];
    const float* W_aggr  = (const float*)d_in[7];
    const float* b_aggr  = (const float*)d_in[8];
    const float* gamma   = (const float*)d_in[9];
    const float* beta    = (const float*)d_in[10];
    const float* W_final = (const float*)d_in[11];
    const float* b_final = (const float*)d_in[12];
    float* out = (float*)d_out;

    const int M = in_sizes[0] / IN_DIM;     // 65536
    const int E = in_sizes[1] / 2;          // 524288

    float *px, *pxi, *pui, *pu, *pug, *pweff, *pbeff;
    __nv_bfloat16 *pxh, *pxl, *pinh, *pinl, *pwh, *pwl;
    double *ps1, *ps2;
    int *pdeg, *prows, *pcur, *pssrc;
    cudaGetSymbolAddress((void**)&px,    g_x);
    cudaGetSymbolAddress((void**)&pxh,   g_xh);
    cudaGetSymbolAddress((void**)&pxl,   g_xl);
    cudaGetSymbolAddress((void**)&pinh,  g_inh);
    cudaGetSymbolAddress((void**)&pinl,  g_inl);
    cudaGetSymbolAddress((void**)&pwh,   g_wh);
    cudaGetSymbolAddress((void**)&pwl,   g_wl);
    cudaGetSymbolAddress((void**)&pxi,   g_xi);
    cudaGetSymbolAddress((void**)&pui,   g_ui);
    cudaGetSymbolAddress((void**)&pu,    g_u);
    cudaGetSymbolAddress((void**)&pug,   g_ug);
    cudaGetSymbolAddress((void**)&ps1,   g_S1);
    cudaGetSymbolAddress((void**)&ps2,   g_S2);
    cudaGetSymbolAddress((void**)&pweff, g_weff);
    cudaGetSymbolAddress((void**)&pbeff, g_beff);
    cudaGetSymbolAddress((void**)&pdeg,  g_deg);
    cudaGetSymbolAddress((void**)&prows, g_rows);
    cudaGetSymbolAddress((void**)&pcur,  g_cur);
    cudaGetSymbolAddress((void**)&pssrc, g_ssrc);

    cudaFuncSetAttribute(gemm_mma_kernel,
                         cudaFuncAttributeMaxDynamicSharedMemorySize, SMEM_MM);

    const int gblk = M / 128;               // 512

    // 1: weight pre-conversion   2: input split   3: CSR zero
    wconv_kernel<<<(W_TOTAL + 255) / 256, 256>>>(W_proj, W_lay, W_aggr, pwh, pwl);
    split_kernel<<<(M * IN_DIM / 4 + 255) / 256, 256>>>(x_in, pinh, pinl, M * IN_DIM / 4);
    zero_int_kernel<<<(M + 1023) / 1024, 1024>>>(pdeg, M);
    // 4: projection GEMM  (the launch ncu captures)
    gemm_mma_kernel<<<gblk, 256, SMEM_MM>>>(pinh, pinl, pwh + OFF_PROJ, pwl + OFF_PROJ,
                                            b_proj, px, pxh, pxl, IN_DIM, 1);
    // CSR build continues
    hist_kernel<<<(E + 255) / 256, 256>>>(ei, pdeg, E);
    scan_kernel<<<1, 1024>>>(pdeg, prows, pcur);
    fill_kernel<<<(E + 255) / 256, 256>>>(ei, pcur, pssrc, E);

    for (int l = 0; l < LAYERS; l++) {
        gemm_mma_kernel<<<gblk, 256, SMEM_MM>>>(pxh, pxl, pwh + OFF_L(l), pwl + OFF_L(l),
                                                b_lay + l * HID, pxi, nullptr, nullptr, HID, 0);
        gemm_mma_kernel<<<gblk, 256, SMEM_MM>>>(pxh, pxl, pwh + OFF_A(l), pwl + OFF_A(l),
                                                b_aggr + l * HID, pui, nullptr, nullptr, HID, 0);
        agg_fuse_kernel<<<M / 8, 256>>>(pui, prows, pssrc, pxi, pu, px, pxh, pxl);
    }

    graph_reduce_kernel<<<GRAPHS, HID>>>(pu, pug);
    zero_stats_kernel<<<1, 256>>>(ps1, ps2);
    xstats_kernel<<<M / 128, HID>>>(px, ps1, ps2);
    ugstats_kernel<<<1, HID>>>(pug, ps1, ps2);
    prep_kernel<<<1, 256>>>(ps1, ps2, gamma, beta, W_final, b_final, pweff, pbeff);
    final_kernel<<<M / 256, 256>>>(px, pug, pweff, pbeff, out);

    (void)n_in; (void)out_size;
}

// round 11
// speedup vs baseline: 1.0876x; 1.0072x over previous
#include <cuda_runtime.h>
#include <cuda_bf16.h>
#include <cstdint>

#define N_NODES   65536
#define N_EDGES   524288
#define HID       128
#define IN_DIM    64
#define GRAPHS    64
#define NODES_PG  1024
#define LAYERS    3

// weight buffer layout (bf16 hi/lo, [n][k] row-major, k contiguous)
#define OFF_PROJ  0                          // 128 n x 64 k
#define W_TOTAL   (8192 + 6 * 16384)         // 106496
#define OFF_L(l)  (8192 + (2 * (l)) * 16384)
#define OFF_A(l)  (8192 + (2 * (l) + 1) * 16384)

// ---------------- scratch (static device globals: allocation-free) ----------
__device__ float          g_x  [N_NODES * HID];
__device__ __nv_bfloat16  g_xh [N_NODES * HID];
__device__ __nv_bfloat16  g_xl [N_NODES * HID];
__device__ __nv_bfloat16  g_inh[N_NODES * IN_DIM];
__device__ __nv_bfloat16  g_inl[N_NODES * IN_DIM];
__device__ __nv_bfloat16  g_wh [W_TOTAL];
__device__ __nv_bfloat16  g_wl [W_TOTAL];
__device__ float          g_xi [N_NODES * HID];
__device__ float          g_ui [N_NODES * HID];
__device__ float          g_u  [N_NODES * HID];
__device__ float          g_ug [GRAPHS * HID];
__device__ double         g_S1 [2 * HID];
__device__ double         g_S2 [2 * HID];
__device__ float          g_weff[2 * HID * 2];
__device__ float          g_beff[2];
// CSR scratch
__device__ int            g_deg [N_NODES];
__device__ int            g_rows[N_NODES + 1];
__device__ int            g_cur [N_NODES];
__device__ int            g_ssrc[N_EDGES];

// ======================= mma.sync helpers (sm_80+) ===========================
__device__ __forceinline__ uint32_t smem_to_u32(const void* p) {
    uint32_t a;
    asm("{ .reg .u64 t; cvta.to.shared.u64 t, %1; cvt.u32.u64 %0, t; }"
        : "=r"(a) : "l"(p));
    return a;
}
__device__ __forceinline__ void ldmatrix_x4(uint32_t* r, uint32_t addr) {
    asm volatile("ldmatrix.sync.aligned.m8n8.x4.shared.b16 {%0,%1,%2,%3}, [%4];"
                 : "=r"(r[0]), "=r"(r[1]), "=r"(r[2]), "=r"(r[3]) : "r"(addr));
}
__device__ __forceinline__ void mma16816(float* c, const uint32_t* a, const uint32_t* b) {
    asm volatile(
        "mma.sync.aligned.m16n8k16.row.col.f32.bf16.bf16.f32 "
        "{%0,%1,%2,%3}, {%4,%5,%6,%7}, {%8,%9}, {%0,%1,%2,%3};"
        : "+f"(c[0]), "+f"(c[1]), "+f"(c[2]), "+f"(c[3])
        : "r"(a[0]), "r"(a[1]), "r"(a[2]), "r"(a[3]), "r"(b[0]), "r"(b[1]));
}

// SMEM layout for gemm (dynamic). Row stride 144 B: 16B aligned, conflict-free
// for 8-row ldmatrix (rows cover all 32 banks exactly once).
#define PSB      144
#define S_BIAS   0
#define S_AHI    512
#define S_ALO    (S_AHI + 128 * PSB)
#define S_BHI    (S_ALO + 128 * PSB)
#define S_BLO    (S_BHI + 128 * PSB)
#define SMEM_MM  (S_BLO + 128 * PSB)

// ========== GEMM: C[M,128] = act(A[M,K] @ B^T + b), HMMA bf16x2 =============
// A hi/lo bf16 [M,K]; B hi/lo bf16 [128,K] (pre-transposed weights).
// D = Ahi*Bhi + Ahi*Blo + Alo*Bhi, fp32 accum.
// CTA: 128 rows x 128 cols, 256 threads, 8 warps in a 4 (M) x 2 (N) grid:
// warp tile = 32 M x 64 N.  A frags shared by 2 warps, B frags by 4 warps ->
// LDSM crossbar bytes cut 1.5x vs 16x128 warp tile (MMA/LDSM 2.67 -> 4.0).
// B pairs double-buffered with one-pair lookahead.
__global__ __launch_bounds__(256, 2) void gemm_mma_kernel(
    const __nv_bfloat16* __restrict__ Ahi, const __nv_bfloat16* __restrict__ Alo,
    const __nv_bfloat16* __restrict__ Bhi, const __nv_bfloat16* __restrict__ Blo,
    const float* __restrict__ bias,
    float* __restrict__ C,
    __nv_bfloat16* __restrict__ Chi, __nv_bfloat16* __restrict__ Clo,
    int K, int relu)
{
    extern __shared__ char smem[];
    const uint32_t sb = smem_to_u32(smem);
    const int tid  = threadIdx.x;
    const int wid  = tid >> 5;
    const int lane = tid & 31;
    const int row0 = blockIdx.x * 128;
    const int m0   = (wid & 3) * 32;     // warp's M offset (32 rows)
    const int n0   = (wid >> 2) * 64;    // warp's N offset (64 cols)
    float* bias_s = (float*)(smem + S_BIAS);
    if (tid < 128) bias_s[tid] = bias[tid];

    float acc[2][8][4];
#pragma unroll
    for (int mt = 0; mt < 2; mt++)
#pragma unroll
        for (int nt = 0; nt < 8; nt++) {
            acc[mt][nt][0]=0.f; acc[mt][nt][1]=0.f;
            acc[mt][nt][2]=0.f; acc[mt][nt][3]=0.f;
        }

    const int kq  = K >> 3;          // uint4 per row
    const int nch = K >> 6;          // chunks of 64 k
    for (int kc = 0; kc < nch; kc++) {
        const uint4* AH4 = (const uint4*)Ahi;
        const uint4* AL4 = (const uint4*)Alo;
        const uint4* BH4 = (const uint4*)Bhi;
        const uint4* BL4 = (const uint4*)Blo;
        // A chunk: 128 rows x 64 k, hi+lo (2048 uint4)
#pragma unroll
        for (int it = 0; it < 8; it++) {
            int i  = tid + it * 256;
            int bf = i >> 10;
            int r  = (i >> 3) & 127;
            int c8 = i & 7;
            const uint4* src = bf ? AL4 : AH4;
            uint4 v = src[(size_t)(row0 + r) * kq + kc * 8 + c8];
            *(uint4*)(smem + (bf ? S_ALO : S_AHI) + r * PSB + c8 * 16) = v;
        }
        // B chunk: 128 n-rows x 64 k, hi+lo (2048 uint4)
#pragma unroll
        for (int it = 0; it < 8; it++) {
            int i  = tid + it * 256;
            int bf = i >> 10;
            int r  = (i >> 3) & 127;
            int c8 = i & 7;
            const uint4* src = bf ? BL4 : BH4;
            uint4 v = src[(size_t)r * kq + kc * 8 + c8];
            *(uint4*)(smem + (bf ? S_BLO : S_BHI) + r * PSB + c8 * 16) = v;
        }
        __syncthreads();

#pragma unroll
        for (int ks = 0; ks < 4; ks++) {
            // A fragments: 2 m-tiles (32 rows), hi + lo
            uint32_t ah[2][4], al[2][4];
#pragma unroll
            for (int mt = 0; mt < 2; mt++) {
                uint32_t aaddr = sb + S_AHI + (m0 + mt * 16 + (lane & 15)) * PSB
                               + ks * 32 + (lane >> 4) * 16;
                ldmatrix_x4(ah[mt], aaddr);
                ldmatrix_x4(al[mt], aaddr + (S_ALO - S_AHI));
            }
            // B pairs within this warp's 64-col half: pair p covers n-tiles
            // (2p, 2p+1) of the half; x4 lane map as in R8/R9 (HW-validated).
            uint32_t bh[2][4], bl[2][4];
            const uint32_t bbase = sb + S_BHI
                + (n0 + ((lane >> 4) & 1) * 8 + (lane & 7)) * PSB
                + ks * 32 + ((lane >> 3) & 1) * 16;
            ldmatrix_x4(bh[0], bbase);
            ldmatrix_x4(bl[0], bbase + (S_BLO - S_BHI));
#pragma unroll
            for (int p = 0; p < 4; p++) {
                const int cur = p & 1, nxt = cur ^ 1;
                if (p < 3) {
                    uint32_t nb = bbase + (p + 1) * (16 * PSB);
                    ldmatrix_x4(bh[nxt], nb);
                    ldmatrix_x4(bl[nxt], nb + (S_BLO - S_BHI));
                }
#pragma unroll
                for (int mt = 0; mt < 2; mt++) {
                    mma16816(acc[mt][2*p],     ah[mt], &bh[cur][0]);
                    mma16816(acc[mt][2*p],     ah[mt], &bl[cur][0]);
                    mma16816(acc[mt][2*p],     al[mt], &bh[cur][0]);
                    mma16816(acc[mt][2*p + 1], ah[mt], &bh[cur][2]);
                    mma16816(acc[mt][2*p + 1], ah[mt], &bl[cur][2]);
                    mma16816(acc[mt][2*p + 1], al[mt], &bh[cur][2]);
                }
            }
        }
        __syncthreads();
    }

    // epilogue: bias(+relu), store fp32 (+ optional bf16 hi/lo split)
    const int group = lane >> 2, tg = lane & 3;
#pragma unroll
    for (int mt = 0; mt < 2; mt++) {
        const int r0 = row0 + m0 + mt * 16 + group;
        const int r1 = r0 + 8;
#pragma unroll
        for (int nt = 0; nt < 8; nt++) {
            int col = n0 + nt * 8 + tg * 2;
            float b0 = bias_s[col], b1 = bias_s[col + 1];
            float o00 = acc[mt][nt][0] + b0, o01 = acc[mt][nt][1] + b1;
            float o10 = acc[mt][nt][2] + b0, o11 = acc[mt][nt][3] + b1;
            if (relu) {
                o00 = fmaxf(o00, 0.f); o01 = fmaxf(o01, 0.f);
                o10 = fmaxf(o10, 0.f); o11 = fmaxf(o11, 0.f);
            }
            ((float2*)C)[((size_t)r0 * 128 + col) >> 1] = make_float2(o00, o01);
            ((float2*)C)[((size_t)r1 * 128 + col) >> 1] = make_float2(o10, o11);
            if (Chi) {
                __nv_bfloat162 h0, h1, l0, l1;
                h0.x = __float2bfloat16(o00); h0.y = __float2bfloat16(o01);
                h1.x = __float2bfloat16(o10); h1.y = __float2bfloat16(o11);
                l0.x = __float2bfloat16(o00 - __bfloat162float(h0.x));
                l0.y = __float2bfloat16(o01 - __bfloat162float(h0.y));
                l1.x = __float2bfloat16(o10 - __bfloat162float(h1.x));
                l1.y = __float2bfloat16(o11 - __bfloat162float(h1.y));
                size_t i0 = ((size_t)r0 * 128 + col) >> 1;
                size_t i1 = ((size_t)r1 * 128 + col) >> 1;
                ((__nv_bfloat162*)Chi)[i0] = h0;
                ((__nv_bfloat162*)Chi)[i1] = h1;
                ((__nv_bfloat162*)Clo)[i0] = l0;
                ((__nv_bfloat162*)Clo)[i1] = l1;
            }
        }
    }
}

// ---------------- weight pre-conversion: fp32 [K,128] -> bf16 hi/lo [n][k] ---
__global__ void wconv_kernel(const float* __restrict__ Wproj,
                             const float* __restrict__ Wlay,
                             const float* __restrict__ Waggr,
                             __nv_bfloat16* __restrict__ wh,
                             __nv_bfloat16* __restrict__ wl)
{
    int i = blockIdx.x * blockDim.x + threadIdx.x;
    if (i >= W_TOTAL) return;
    float v;
    if (i < 8192) {
        int n = i >> 6, k = i & 63;
        v = Wproj[k * 128 + n];
    } else {
        int j = i - 8192;
        int m = j >> 14;
        int r = j & 16383;
        int n = r >> 7, k = r & 127;
        int l = m >> 1;
        const float* src = (m & 1) ? Waggr : Wlay;
        v = src[(size_t)l * 16384 + k * 128 + n];
    }
    __nv_bfloat16 h = __float2bfloat16(v);
    wh[i] = h;
    wl[i] = __float2bfloat16(v - __bfloat162float(h));
}

// ---------------- split fp32 -> bf16 hi/lo -----------------------------------
__global__ void split_kernel(const float* __restrict__ src,
                             __nv_bfloat16* __restrict__ hi,
                             __nv_bfloat16* __restrict__ lo, int n4)
{
    int i = blockIdx.x * blockDim.x + threadIdx.x;
    if (i >= n4) return;
    float4 v = ((const float4*)src)[i];
    __nv_bfloat162 h0, h1, l0, l1;
    h0.x = __float2bfloat16(v.x); h0.y = __float2bfloat16(v.y);
    h1.x = __float2bfloat16(v.z); h1.y = __float2bfloat16(v.w);
    l0.x = __float2bfloat16(v.x - __bfloat162float(h0.x));
    l0.y = __float2bfloat16(v.y - __bfloat162float(h0.y));
    l1.x = __float2bfloat16(v.z - __bfloat162float(h1.x));
    l1.y = __float2bfloat16(v.w - __bfloat162float(h1.y));
    ((__nv_bfloat162*)hi)[2 * i]     = h0;
    ((__nv_bfloat162*)hi)[2 * i + 1] = h1;
    ((__nv_bfloat162*)lo)[2 * i]     = l0;
    ((__nv_bfloat162*)lo)[2 * i + 1] = l1;
}

// ================= CSR build (once per launch) ===============================
__global__ void zero_int_kernel(int* __restrict__ p, int n)
{
    int i = blockIdx.x * blockDim.x + threadIdx.x;
    if (i < n) p[i] = 0;
}
__global__ void hist_kernel(const int* __restrict__ ei, int* __restrict__ deg, int E)
{
    int i = blockIdx.x * blockDim.x + threadIdx.x;
    if (i < E) atomicAdd(&deg[ei[E + i]], 1);
}
__global__ void scan_kernel(const int* __restrict__ deg, int* __restrict__ rows,
                            int* __restrict__ cur)
{
    __shared__ int part[1024];
    int t = threadIdx.x;
    int base = t * 64;
    int s = 0;
#pragma unroll 8
    for (int i = 0; i < 64; i++) s += deg[base + i];
    part[t] = s;
    __syncthreads();
    for (int off = 1; off < 1024; off <<= 1) {
        int v = (t >= off) ? part[t - off] : 0;
        __syncthreads();
        part[t] += v;
        __syncthreads();
    }
    int run = part[t] - s;
    for (int i = 0; i < 64; i++) {
        rows[base + i] = run;
        cur[base + i]  = run;
        run += deg[base + i];
    }
    if (t == 1023) rows[N_NODES] = part[1023];
}
__global__ void fill_kernel(const int* __restrict__ ei, int* __restrict__ cur,
                            int* __restrict__ ssrc, int E)
{
    int e = blockIdx.x * blockDim.x + threadIdx.x;
    if (e >= E) return;
    int d = ei[E + e];
    int p = atomicAdd(&cur[d], 1);
    ssrc[p] = ei[e];
}

// ---- fused: u[n] = sum ui[src]; x = relu(xi + u); emit x fp32 + bf16 hi/lo --
__global__ __launch_bounds__(256) void agg_fuse_kernel(
    const float* __restrict__ ui, const int* __restrict__ rows,
    const int* __restrict__ ssrc, const float* __restrict__ xi,
    float* __restrict__ u, float* __restrict__ x,
    __nv_bfloat16* __restrict__ xh, __nv_bfloat16* __restrict__ xl)
{
    int w    = blockIdx.x * 8 + (threadIdx.x >> 5);
    int lane = threadIdx.x & 31;
    int st = rows[w], en = rows[w + 1];
    float4 a = make_float4(0.f, 0.f, 0.f, 0.f);
    float4 b = make_float4(0.f, 0.f, 0.f, 0.f);
    const float4* ui4 = (const float4*)ui;
    int e = st;
    for (; e + 1 < en; e += 2) {
        int s0 = __ldg(&ssrc[e]);
        int s1 = __ldg(&ssrc[e + 1]);
        float4 v0 = __ldg(&ui4[(size_t)s0 * 32 + lane]);
        float4 v1 = __ldg(&ui4[(size_t)s1 * 32 + lane]);
        a.x += v0.x; a.y += v0.y; a.z += v0.z; a.w += v0.w;
        b.x += v1.x; b.y += v1.y; b.z += v1.z; b.w += v1.w;
    }
    if (e < en) {
        int s0 = __ldg(&ssrc[e]);
        float4 v0 = __ldg(&ui4[(size_t)s0 * 32 + lane]);
        a.x += v0.x; a.y += v0.y; a.z += v0.z; a.w += v0.w;
    }
    a.x += b.x; a.y += b.y; a.z += b.z; a.w += b.w;
    size_t idx = (size_t)w * 32 + lane;
    ((float4*)u)[idx] = a;
    float4 t = ((const float4*)xi)[idx];
    float4 o;
    o.x = fmaxf(t.x + a.x, 0.f);
    o.y = fmaxf(t.y + a.y, 0.f);
    o.z = fmaxf(t.z + a.z, 0.f);
    o.w = fmaxf(t.w + a.w, 0.f);
    ((float4*)x)[idx] = o;
    __nv_bfloat162 h0, h1, l0, l1;
    h0.x = __float2bfloat16(o.x); h0.y = __float2bfloat16(o.y);
    h1.x = __float2bfloat16(o.z); h1.y = __float2bfloat16(o.w);
    l0.x = __float2bfloat16(o.x - __bfloat162float(h0.x));
    l0.y = __float2bfloat16(o.y - __bfloat162float(h0.y));
    l1.x = __float2bfloat16(o.z - __bfloat162float(h1.x));
    l1.y = __float2bfloat16(o.w - __bfloat162float(h1.y));
    ((__nv_bfloat162*)xh)[2 * idx]     = h0;
    ((__nv_bfloat162*)xh)[2 * idx + 1] = h1;
    ((__nv_bfloat162*)xl)[2 * idx]     = l0;
    ((__nv_bfloat162*)xl)[2 * idx + 1] = l1;
}

// ---------------- per-graph sum of u -----------------------------------------
__global__ void graph_reduce_kernel(const float* __restrict__ u,
                                    float* __restrict__ ug)
{
    int g = blockIdx.x;
    int c = threadIdx.x;
    const float* base = u + (size_t)g * NODES_PG * HID + c;
    float s = 0.f;
#pragma unroll 8
    for (int r = 0; r < NODES_PG; r++) s += base[(size_t)r * HID];
    ug[g * HID + c] = s;
}

// ---------------- column stats -----------------------------------------------
__global__ void zero_stats_kernel(double* __restrict__ s1, double* __restrict__ s2)
{
    int i = threadIdx.x;
    s1[i] = 0.0; s2[i] = 0.0;
}
__global__ void xstats_kernel(const float* __restrict__ x,
                              double* __restrict__ S1, double* __restrict__ S2)
{
    int c = threadIdx.x;
    int b = blockIdx.x;
    const float* base = x + (size_t)b * 128 * HID + c;
    float s1 = 0.f, s2 = 0.f;
#pragma unroll 8
    for (int r = 0; r < 128; r++) {
        float v = base[(size_t)r * HID];
        s1 += v; s2 += v * v;
    }
    atomicAdd(&S1[c], (double)s1);
    atomicAdd(&S2[c], (double)s2);
}
__global__ void ugstats_kernel(const float* __restrict__ ug,
                               double* __restrict__ S1, double* __restrict__ S2)
{
    int c = threadIdx.x;
    double s1 = 0.0, s2 = 0.0;
    for (int g = 0; g < GRAPHS; g++) {
        double v = (double)ug[g * HID + c];
        s1 += v; s2 += v * v;
    }
    S1[HID + c] = s1;
    S2[HID + c] = s2;
}

// ---------------- fold BN into final linear ----------------------------------
__global__ void prep_kernel(const double* __restrict__ S1, const double* __restrict__ S2,
                            const float* __restrict__ gamma, const float* __restrict__ beta,
                            const float* __restrict__ Wf, const float* __restrict__ bf,
                            float* __restrict__ weff, float* __restrict__ beff)
{
    __shared__ float r0[256], r1[256];
    int c = threadIdx.x;
    double div  = (c < HID) ? (double)N_NODES : (double)GRAPHS;
    double mean = S1[c] / div;
    double var  = S2[c] / div - mean * mean;
    float  s     = gamma[c] * rsqrtf((float)var + 1e-5f);
    float  shift = beta[c] - (float)mean * s;
    float  w0 = Wf[c * 2 + 0], w1 = Wf[c * 2 + 1];
    weff[c * 2 + 0] = s * w0;
    weff[c * 2 + 1] = s * w1;
    r0[c] = shift * w0;
    r1[c] = shift * w1;
    __syncthreads();
    for (int st = 128; st > 0; st >>= 1) {
        if (c < st) { r0[c] += r0[c + st]; r1[c] += r1[c + st]; }
        __syncthreads();
    }
    if (c == 0) { beff[0] = bf[0] + r0[0]; beff[1] = bf[1] + r1[0]; }
}

// ---------------- final: out[n] = [x_n | ug_g] @ Weff + beff -----------------
__global__ __launch_bounds__(256) void final_kernel(
    const float* __restrict__ x, const float* __restrict__ ug,
    const float* __restrict__ weff, const float* __restrict__ beff,
    float* __restrict__ out)
{
    __shared__ float wsh[512];
    __shared__ float ush[HID];
    __shared__ float bsh[2];
    int tid = threadIdx.x;
    int n0  = blockIdx.x * 256;
    wsh[tid]       = weff[tid];
    wsh[tid + 256] = weff[tid + 256];
    if (tid < 2)   bsh[tid] = beff[tid];
    int g = n0 >> 10;
    if (tid < HID) ush[tid] = ug[g * HID + tid];
    __syncthreads();

    int n = n0 + tid;
    float a0 = bsh[0], a1 = bsh[1];
    const float4* xr = (const float4*)(x + (size_t)n * HID);
#pragma unroll
    for (int c4 = 0; c4 < 32; c4++) {
        float4 v = xr[c4];
        int c = c4 * 4;
        a0 += v.x * wsh[2*c+0] + v.y * wsh[2*c+2] + v.z * wsh[2*c+4] + v.w * wsh[2*c+6];
        a1 += v.x * wsh[2*c+1] + v.y * wsh[2*c+3] + v.z * wsh[2*c+5] + v.w * wsh[2*c+7];
    }
#pragma unroll 8
    for (int c = 0; c < HID; c++) {
        float uv = ush[c];
        a0 += uv * wsh[2 * (HID + c) + 0];
        a1 += uv * wsh[2 * (HID + c) + 1];
    }
    out[n * 2 + 0] = a0;
    out[n * 2 + 1] = a1;
}

// ---------------- host orchestration ----------------------------------------
extern "C" void kernel_launch(void* const* d_in, const int* in_sizes, int n_in,
                              void* d_out, int out_size)
{
    const float* x_in    = (const float*)d_in[0];
    const int*   ei      = (const int*)  d_in[1];
    const float* W_proj  = (const float*)d_in[3];
    const float* b_proj  = (const float*)d_in[4];
    const float* W_lay   = (const float*)d_in[5];
    const float* b_lay   = (const float*)d_in[6];
    const float* W_aggr  = (const float*)d_in[7];
    const float* b_aggr  = (const float*)d_in[8];
    const float* gamma   = (const float*)d_in[9];
    const float* beta    = (const float*)d_in[10];
    const float* W_final = (const float*)d_in[11];
    const float* b_final = (const float*)d_in[12];
    float* out = (float*)d_out;

    const int M = in_sizes[0] / IN_DIM;     // 65536
    const int E = in_sizes[1] / 2;          // 524288

    float *px, *pxi, *pui, *pu, *pug, *pweff, *pbeff;
    __nv_bfloat16 *pxh, *pxl, *pinh, *pinl, *pwh, *pwl;
    double *ps1, *ps2;
    int *pdeg, *prows, *pcur, *pssrc;
    cudaGetSymbolAddress((void**)&px,    g_x);
    cudaGetSymbolAddress((void**)&pxh,   g_xh);
    cudaGetSymbolAddress((void**)&pxl,   g_xl);
    cudaGetSymbolAddress((void**)&pinh,  g_inh);
    cudaGetSymbolAddress((void**)&pinl,  g_inl);
    cudaGetSymbolAddress((void**)&pwh,   g_wh);
    cudaGetSymbolAddress((void**)&pwl,   g_wl);
    cudaGetSymbolAddress((void**)&pxi,   g_xi);
    cudaGetSymbolAddress((void**)&pui,   g_ui);
    cudaGetSymbolAddress((void**)&pu,    g_u);
    cudaGetSymbolAddress((void**)&pug,   g_ug);
    cudaGetSymbolAddress((void**)&ps1,   g_S1);
    cudaGetSymbolAddress((void**)&ps2,   g_S2);
    cudaGetSymbolAddress((void**)&pweff, g_weff);
    cudaGetSymbolAddress((void**)&pbeff, g_beff);
    cudaGetSymbolAddress((void**)&pdeg,  g_deg);
    cudaGetSymbolAddress((void**)&prows, g_rows);
    cudaGetSymbolAddress((void**)&pcur,  g_cur);
    cudaGetSymbolAddress((void**)&pssrc, g_ssrc);

    cudaFuncSetAttribute(gemm_mma_kernel,
                         cudaFuncAttributeMaxDynamicSharedMemorySize, SMEM_MM);

    const int gblk = M / 128;               // 512

    // 1: weight pre-conversion   2: input split   3: CSR zero
    wconv_kernel<<<(W_TOTAL + 255) / 256, 256>>>(W_proj, W_lay, W_aggr, pwh, pwl);
    split_kernel<<<(M * IN_DIM / 4 + 255) / 256, 256>>>(x_in, pinh, pinl, M * IN_DIM / 4);
    zero_int_kernel<<<(M + 1023) / 1024, 1024>>>(pdeg, M);
    // 4: projection GEMM  (the launch ncu captures)
    gemm_mma_kernel<<<gblk, 256, SMEM_MM>>>(pinh, pinl, pwh + OFF_PROJ, pwl + OFF_PROJ,
                                            b_proj, px, pxh, pxl, IN_DIM, 1);
    // CSR build continues
    hist_kernel<<<(E + 255) / 256, 256>>>(ei, pdeg, E);
    scan_kernel<<<1, 1024>>>(pdeg, prows, pcur);
    fill_kernel<<<(E + 255) / 256, 256>>>(ei, pcur, pssrc, E);

    for (int l = 0; l < LAYERS; l++) {
        gemm_mma_kernel<<<gblk, 256, SMEM_MM>>>(pxh, pxl, pwh + OFF_L(l), pwl + OFF_L(l),
                                                b_lay + l * HID, pxi, nullptr, nullptr, HID, 0);
        gemm_mma_kernel<<<gblk, 256, SMEM_MM>>>(pxh, pxl, pwh + OFF_A(l), pwl + OFF_A(l),
                                                b_aggr + l * HID, pui, nullptr, nullptr, HID, 0);
        agg_fuse_kernel<<<M / 8, 256>>>(pui, prows, pssrc, pxi, pu, px, pxh, pxl);
    }

    graph_reduce_kernel<<<GRAPHS, HID>>>(pu, pug);
    zero_stats_kernel<<<1, 256>>>(ps1, ps2);
    xstats_kernel<<<M / 128, HID>>>(px, ps1, ps2);
    ugstats_kernel<<<1, HID>>>(pug, ps1, ps2);
    prep_kernel<<<1, 256>>>(ps1, ps2, gamma, beta, W_final, b_final, pweff, pbeff);
    final_kernel<<<M / 256, 256>>>(px, pug, pweff, pbeff, out);

    (void)n_in; (void)out_size;
}

// round 12
// speedup vs baseline: 1.1107x; 1.0213x over previous
#include <cuda_runtime.h>
#include <cuda_bf16.h>
#include <cstdint>

#define N_NODES   65536
#define N_EDGES   524288
#define HID       128
#define IN_DIM    64
#define GRAPHS    64
#define NODES_PG  1024
#define LAYERS    3

// weight buffer layout (bf16 hi/lo, [n][k] row-major, k contiguous)
#define OFF_PROJ  0                          // 128 n x 64 k
#define W_TOTAL   (8192 + 6 * 16384)         // 106496
#define OFF_L(l)  (8192 + (2 * (l)) * 16384)
#define OFF_A(l)  (8192 + (2 * (l) + 1) * 16384)   // = OFF_L(l) + 16384

// ---------------- scratch (static device globals: allocation-free) ----------
__device__ __nv_bfloat16  g_xh [N_NODES * HID];
__device__ __nv_bfloat16  g_xl [N_NODES * HID];
__device__ __nv_bfloat16  g_inh[N_NODES * IN_DIM];
__device__ __nv_bfloat16  g_inl[N_NODES * IN_DIM];
__device__ __nv_bfloat16  g_wh [W_TOTAL];
__device__ __nv_bfloat16  g_wl [W_TOTAL];
__device__ float          g_xi [N_NODES * HID];
__device__ float          g_ui [N_NODES * HID];
__device__ float          g_u  [N_NODES * HID];
__device__ float          g_ug [GRAPHS * HID];
__device__ double         g_S1 [2 * HID];
__device__ double         g_S2 [2 * HID];
__device__ float          g_weff[2 * HID * 2];
__device__ float          g_beff[2];
// CSR scratch
__device__ int            g_deg [N_NODES];
__device__ int            g_rows[N_NODES + 1];
__device__ int            g_cur [N_NODES];
__device__ int            g_ssrc[N_EDGES];

// ======================= mma.sync helpers (sm_80+) ===========================
__device__ __forceinline__ uint32_t smem_to_u32(const void* p) {
    uint32_t a;
    asm("{ .reg .u64 t; cvta.to.shared.u64 t, %1; cvt.u32.u64 %0, t; }"
        : "=r"(a) : "l"(p));
    return a;
}
__device__ __forceinline__ void ldmatrix_x4(uint32_t* r, uint32_t addr) {
    asm volatile("ldmatrix.sync.aligned.m8n8.x4.shared.b16 {%0,%1,%2,%3}, [%4];"
                 : "=r"(r[0]), "=r"(r[1]), "=r"(r[2]), "=r"(r[3]) : "r"(addr));
}
__device__ __forceinline__ void mma16816(float* c, const uint32_t* a, const uint32_t* b) {
    asm volatile(
        "mma.sync.aligned.m16n8k16.row.col.f32.bf16.bf16.f32 "
        "{%0,%1,%2,%3}, {%4,%5,%6,%7}, {%8,%9}, {%0,%1,%2,%3};"
        : "+f"(c[0]), "+f"(c[1]), "+f"(c[2]), "+f"(c[3])
        : "r"(a[0]), "r"(a[1]), "r"(a[2]), "r"(a[3]), "r"(b[0]), "r"(b[1]));
}

// SMEM layout for gemm (dynamic). Row stride 144 B: 16B aligned, conflict-free
// for 8-row ldmatrix (rows cover all 32 banks exactly once).
#define PSB      144
#define S_BIAS   0
#define S_AHI    512
#define S_ALO    (S_AHI + 128 * PSB)
#define S_BHI    (S_ALO + 128 * PSB)
#define S_BLO    (S_BHI + 128 * PSB)
#define SMEM_MM  (S_BLO + 128 * PSB)

// ========== GEMM: C[M,128] = act(A[M,K] @ B^T + b), HMMA bf16x2 =============
// A hi/lo bf16 [M,K]; B hi/lo bf16 [128,K] (pre-transposed weights).
// D = Ahi*Bhi + Ahi*Blo + Alo*Bhi, fp32 accum.
// Dual-output mode: grid may be 2*512; blockIdx.x>>9 selects weight matrix
// (+16384 elements), bias and C output -> both per-layer GEMMs in ONE launch
// (better wave packing on 148 SMs).
// CTA: 128 rows x 128 cols, 256 threads, 8 warps in 4(M) x 2(N) grid
// (warp tile 32x64); B pairs double-buffered with one-pair lookahead.
__global__ __launch_bounds__(256, 2) void gemm_mma_kernel(
    const __nv_bfloat16* __restrict__ Ahi, const __nv_bfloat16* __restrict__ Alo,
    const __nv_bfloat16* __restrict__ Bhi_, const __nv_bfloat16* __restrict__ Blo_,
    const float* __restrict__ bias0, const float* __restrict__ bias1,
    float* __restrict__ C0, float* __restrict__ C1,
    __nv_bfloat16* __restrict__ Chi, __nv_bfloat16* __restrict__ Clo,
    int K, int relu)
{
    extern __shared__ char smem[];
    const uint32_t sb = smem_to_u32(smem);
    const int tid  = threadIdx.x;
    const int wid  = tid >> 5;
    const int lane = tid & 31;
    const int bsel = blockIdx.x >> 9;          // 0 or 1 (dual-launch select)
    const int row0 = (blockIdx.x & 511) * 128;
    const int m0   = (wid & 3) * 32;
    const int n0   = (wid >> 2) * 64;
    const __nv_bfloat16* Bhi = Bhi_ + bsel * 16384;
    const __nv_bfloat16* Blo = Blo_ + bsel * 16384;
    const float* bias = bsel ? bias1 : bias0;
    float* C = bsel ? C1 : C0;
    float* bias_s = (float*)(smem + S_BIAS);
    if (tid < 128) bias_s[tid] = bias[tid];

    float acc[2][8][4];
#pragma unroll
    for (int mt = 0; mt < 2; mt++)
#pragma unroll
        for (int nt = 0; nt < 8; nt++) {
            acc[mt][nt][0]=0.f; acc[mt][nt][1]=0.f;
            acc[mt][nt][2]=0.f; acc[mt][nt][3]=0.f;
        }

    const int kq  = K >> 3;          // uint4 per row
    const int nch = K >> 6;          // chunks of 64 k
    for (int kc = 0; kc < nch; kc++) {
        const uint4* AH4 = (const uint4*)Ahi;
        const uint4* AL4 = (const uint4*)Alo;
        const uint4* BH4 = (const uint4*)Bhi;
        const uint4* BL4 = (const uint4*)Blo;
        // A chunk: 128 rows x 64 k, hi+lo (2048 uint4)
#pragma unroll
        for (int it = 0; it < 8; it++) {
            int i  = tid + it * 256;
            int bf = i >> 10;
            int r  = (i >> 3) & 127;
            int c8 = i & 7;
            const uint4* src = bf ? AL4 : AH4;
            uint4 v = src[(size_t)(row0 + r) * kq + kc * 8 + c8];
            *(uint4*)(smem + (bf ? S_ALO : S_AHI) + r * PSB + c8 * 16) = v;
        }
        // B chunk: 128 n-rows x 64 k, hi+lo (2048 uint4)
#pragma unroll
        for (int it = 0; it < 8; it++) {
            int i  = tid + it * 256;
            int bf = i >> 10;
            int r  = (i >> 3) & 127;
            int c8 = i & 7;
            const uint4* src = bf ? BL4 : BH4;
            uint4 v = src[(size_t)r * kq + kc * 8 + c8];
            *(uint4*)(smem + (bf ? S_BLO : S_BHI) + r * PSB + c8 * 16) = v;
        }
        __syncthreads();

#pragma unroll
        for (int ks = 0; ks < 4; ks++) {
            // A fragments: 2 m-tiles (32 rows), hi + lo
            uint32_t ah[2][4], al[2][4];
#pragma unroll
            for (int mt = 0; mt < 2; mt++) {
                uint32_t aaddr = sb + S_AHI + (m0 + mt * 16 + (lane & 15)) * PSB
                               + ks * 32 + (lane >> 4) * 16;
                ldmatrix_x4(ah[mt], aaddr);
                ldmatrix_x4(al[mt], aaddr + (S_ALO - S_AHI));
            }
            // B pairs within this warp's 64-col half (double-buffered)
            uint32_t bh[2][4], bl[2][4];
            const uint32_t bbase = sb + S_BHI
                + (n0 + ((lane >> 4) & 1) * 8 + (lane & 7)) * PSB
                + ks * 32 + ((lane >> 3) & 1) * 16;
            ldmatrix_x4(bh[0], bbase);
            ldmatrix_x4(bl[0], bbase + (S_BLO - S_BHI));
#pragma unroll
            for (int p = 0; p < 4; p++) {
                const int cur = p & 1, nxt = cur ^ 1;
                if (p < 3) {
                    uint32_t nb = bbase + (p + 1) * (16 * PSB);
                    ldmatrix_x4(bh[nxt], nb);
                    ldmatrix_x4(bl[nxt], nb + (S_BLO - S_BHI));
                }
#pragma unroll
                for (int mt = 0; mt < 2; mt++) {
                    mma16816(acc[mt][2*p],     ah[mt], &bh[cur][0]);
                    mma16816(acc[mt][2*p],     ah[mt], &bl[cur][0]);
                    mma16816(acc[mt][2*p],     al[mt], &bh[cur][0]);
                    mma16816(acc[mt][2*p + 1], ah[mt], &bh[cur][2]);
                    mma16816(acc[mt][2*p + 1], ah[mt], &bl[cur][2]);
                    mma16816(acc[mt][2*p + 1], al[mt], &bh[cur][2]);
                }
            }
        }
        __syncthreads();
    }

    // epilogue: bias(+relu); store fp32 (if C) and/or bf16 hi/lo (if Chi)
    const int group = lane >> 2, tg = lane & 3;
#pragma unroll
    for (int mt = 0; mt < 2; mt++) {
        const int r0 = row0 + m0 + mt * 16 + group;
        const int r1 = r0 + 8;
#pragma unroll
        for (int nt = 0; nt < 8; nt++) {
            int col = n0 + nt * 8 + tg * 2;
            float b0 = bias_s[col], b1 = bias_s[col + 1];
            float o00 = acc[mt][nt][0] + b0, o01 = acc[mt][nt][1] + b1;
            float o10 = acc[mt][nt][2] + b0, o11 = acc[mt][nt][3] + b1;
            if (relu) {
                o00 = fmaxf(o00, 0.f); o01 = fmaxf(o01, 0.f);
                o10 = fmaxf(o10, 0.f); o11 = fmaxf(o11, 0.f);
            }
            if (C) {
                ((float2*)C)[((size_t)r0 * 128 + col) >> 1] = make_float2(o00, o01);
                ((float2*)C)[((size_t)r1 * 128 + col) >> 1] = make_float2(o10, o11);
            }
            if (Chi) {
                __nv_bfloat162 h0, h1, l0, l1;
                h0.x = __float2bfloat16(o00); h0.y = __float2bfloat16(o01);
                h1.x = __float2bfloat16(o10); h1.y = __float2bfloat16(o11);
                l0.x = __float2bfloat16(o00 - __bfloat162float(h0.x));
                l0.y = __float2bfloat16(o01 - __bfloat162float(h0.y));
                l1.x = __float2bfloat16(o10 - __bfloat162float(h1.x));
                l1.y = __float2bfloat16(o11 - __bfloat162float(h1.y));
                size_t i0 = ((size_t)r0 * 128 + col) >> 1;
                size_t i1 = ((size_t)r1 * 128 + col) >> 1;
                ((__nv_bfloat162*)Chi)[i0] = h0;
                ((__nv_bfloat162*)Chi)[i1] = h1;
                ((__nv_bfloat162*)Clo)[i0] = l0;
                ((__nv_bfloat162*)Clo)[i1] = l1;
            }
        }
    }
}

// ---------------- weight pre-conversion: fp32 [K,128] -> bf16 hi/lo [n][k] ---
__global__ void wconv_kernel(const float* __restrict__ Wproj,
                             const float* __restrict__ Wlay,
                             const float* __restrict__ Waggr,
                             __nv_bfloat16* __restrict__ wh,
                             __nv_bfloat16* __restrict__ wl)
{
    int i = blockIdx.x * blockDim.x + threadIdx.x;
    if (i >= W_TOTAL) return;
    float v;
    if (i < 8192) {
        int n = i >> 6, k = i & 63;
        v = Wproj[k * 128 + n];
    } else {
        int j = i - 8192;
        int m = j >> 14;
        int r = j & 16383;
        int n = r >> 7, k = r & 127;
        int l = m >> 1;
        const float* src = (m & 1) ? Waggr : Wlay;
        v = src[(size_t)l * 16384 + k * 128 + n];
    }
    __nv_bfloat16 h = __float2bfloat16(v);
    wh[i] = h;
    wl[i] = __float2bfloat16(v - __bfloat162float(h));
}

// ---------------- split fp32 -> bf16 hi/lo -----------------------------------
__global__ void split_kernel(const float* __restrict__ src,
                             __nv_bfloat16* __restrict__ hi,
                             __nv_bfloat16* __restrict__ lo, int n4)
{
    int i = blockIdx.x * blockDim.x + threadIdx.x;
    if (i >= n4) return;
    float4 v = ((const float4*)src)[i];
    __nv_bfloat162 h0, h1, l0, l1;
    h0.x = __float2bfloat16(v.x); h0.y = __float2bfloat16(v.y);
    h1.x = __float2bfloat16(v.z); h1.y = __float2bfloat16(v.w);
    l0.x = __float2bfloat16(v.x - __bfloat162float(h0.x));
    l0.y = __float2bfloat16(v.y - __bfloat162float(h0.y));
    l1.x = __float2bfloat16(v.z - __bfloat162float(h1.x));
    l1.y = __float2bfloat16(v.w - __bfloat162float(h1.y));
    ((__nv_bfloat162*)hi)[2 * i]     = h0;
    ((__nv_bfloat162*)hi)[2 * i + 1] = h1;
    ((__nv_bfloat162*)lo)[2 * i]     = l0;
    ((__nv_bfloat162*)lo)[2 * i + 1] = l1;
}

// ================= CSR build (once per launch) ===============================
__global__ void zero_int_kernel(int* __restrict__ p, int n)
{
    int i = blockIdx.x * blockDim.x + threadIdx.x;
    if (i < n) p[i] = 0;
}
__global__ void hist_kernel(const int* __restrict__ ei, int* __restrict__ deg, int E)
{
    int i = blockIdx.x * blockDim.x + threadIdx.x;
    if (i < E) atomicAdd(&deg[ei[E + i]], 1);
}
__global__ void scan_kernel(const int* __restrict__ deg, int* __restrict__ rows,
                            int* __restrict__ cur)
{
    __shared__ int part[1024];
    int t = threadIdx.x;
    int base = t * 64;
    int s = 0;
#pragma unroll 8
    for (int i = 0; i < 64; i++) s += deg[base + i];
    part[t] = s;
    __syncthreads();
    for (int off = 1; off < 1024; off <<= 1) {
        int v = (t >= off) ? part[t - off] : 0;
        __syncthreads();
        part[t] += v;
        __syncthreads();
    }
    int run = part[t] - s;
    for (int i = 0; i < 64; i++) {
        rows[base + i] = run;
        cur[base + i]  = run;
        run += deg[base + i];
    }
    if (t == 1023) rows[N_NODES] = part[1023];
}
__global__ void fill_kernel(const int* __restrict__ ei, int* __restrict__ cur,
                            int* __restrict__ ssrc, int E)
{
    int e = blockIdx.x * blockDim.x + threadIdx.x;
    if (e >= E) return;
    int d = ei[E + e];
    int p = atomicAdd(&cur[d], 1);
    ssrc[p] = ei[e];
}

// ---- fused: u = sum ui[src]; x = relu(xi + u) -> bf16 hi/lo only ------------
// u written to gmem only when write_u != 0 (last layer; graph_reduce needs it).
__global__ __launch_bounds__(256) void agg_fuse_kernel(
    const float* __restrict__ ui, const int* __restrict__ rows,
    const int* __restrict__ ssrc, const float* __restrict__ xi,
    float* __restrict__ u,
    __nv_bfloat16* __restrict__ xh, __nv_bfloat16* __restrict__ xl,
    int write_u)
{
    int w    = blockIdx.x * 8 + (threadIdx.x >> 5);
    int lane = threadIdx.x & 31;
    int st = rows[w], en = rows[w + 1];
    float4 a = make_float4(0.f, 0.f, 0.f, 0.f);
    float4 b = make_float4(0.f, 0.f, 0.f, 0.f);
    const float4* ui4 = (const float4*)ui;
    int e = st;
    for (; e + 1 < en; e += 2) {
        int s0 = __ldg(&ssrc[e]);
        int s1 = __ldg(&ssrc[e + 1]);
        float4 v0 = __ldg(&ui4[(size_t)s0 * 32 + lane]);
        float4 v1 = __ldg(&ui4[(size_t)s1 * 32 + lane]);
        a.x += v0.x; a.y += v0.y; a.z += v0.z; a.w += v0.w;
        b.x += v1.x; b.y += v1.y; b.z += v1.z; b.w += v1.w;
    }
    if (e < en) {
        int s0 = __ldg(&ssrc[e]);
        float4 v0 = __ldg(&ui4[(size_t)s0 * 32 + lane]);
        a.x += v0.x; a.y += v0.y; a.z += v0.z; a.w += v0.w;
    }
    a.x += b.x; a.y += b.y; a.z += b.z; a.w += b.w;
    size_t idx = (size_t)w * 32 + lane;
    if (write_u) ((float4*)u)[idx] = a;
    float4 t = ((const float4*)xi)[idx];
    float4 o;
    o.x = fmaxf(t.x + a.x, 0.f);
    o.y = fmaxf(t.y + a.y, 0.f);
    o.z = fmaxf(t.z + a.z, 0.f);
    o.w = fmaxf(t.w + a.w, 0.f);
    __nv_bfloat162 h0, h1, l0, l1;
    h0.x = __float2bfloat16(o.x); h0.y = __float2bfloat16(o.y);
    h1.x = __float2bfloat16(o.z); h1.y = __float2bfloat16(o.w);
    l0.x = __float2bfloat16(o.x - __bfloat162float(h0.x));
    l0.y = __float2bfloat16(o.y - __bfloat162float(h0.y));
    l1.x = __float2bfloat16(o.z - __bfloat162float(h1.x));
    l1.y = __float2bfloat16(o.w - __bfloat162float(h1.y));
    ((__nv_bfloat162*)xh)[2 * idx]     = h0;
    ((__nv_bfloat162*)xh)[2 * idx + 1] = h1;
    ((__nv_bfloat162*)xl)[2 * idx]     = l0;
    ((__nv_bfloat162*)xl)[2 * idx + 1] = l1;
}

// ---------------- per-graph sum of u -----------------------------------------
__global__ void graph_reduce_kernel(const float* __restrict__ u,
                                    float* __restrict__ ug)
{
    int g = blockIdx.x;
    int c = threadIdx.x;
    const float* base = u + (size_t)g * NODES_PG * HID + c;
    float s = 0.f;
#pragma unroll 8
    for (int r = 0; r < NODES_PG; r++) s += base[(size_t)r * HID];
    ug[g * HID + c] = s;
}

// ---------------- column stats (x reconstructed from bf16 hi/lo) -------------
__global__ void zero_stats_kernel(double* __restrict__ s1, double* __restrict__ s2)
{
    int i = threadIdx.x;
    s1[i] = 0.0; s2[i] = 0.0;
}
__global__ void xstats_kernel(const __nv_bfloat16* __restrict__ xh,
                              const __nv_bfloat16* __restrict__ xl,
                              double* __restrict__ S1, double* __restrict__ S2)
{
    int c2 = threadIdx.x;     // 64 column-pairs
    int b  = blockIdx.x;      // 512 blocks x 128 rows
    const __nv_bfloat162* h = (const __nv_bfloat162*)xh + (size_t)b * 128 * 64 + c2;
    const __nv_bfloat162* l = (const __nv_bfloat162*)xl + (size_t)b * 128 * 64 + c2;
    float s1a = 0.f, s2a = 0.f, s1b = 0.f, s2b = 0.f;
#pragma unroll 4
    for (int r = 0; r < 128; r++) {
        __nv_bfloat162 hv = h[(size_t)r * 64];
        __nv_bfloat162 lv = l[(size_t)r * 64];
        float v0 = __bfloat162float(hv.x) + __bfloat162float(lv.x);
        float v1 = __bfloat162float(hv.y) + __bfloat162float(lv.y);
        s1a += v0; s2a += v0 * v0;
        s1b += v1; s2b += v1 * v1;
    }
    atomicAdd(&S1[2 * c2 + 0], (double)s1a);
    atomicAdd(&S2[2 * c2 + 0], (double)s2a);
    atomicAdd(&S1[2 * c2 + 1], (double)s1b);
    atomicAdd(&S2[2 * c2 + 1], (double)s2b);
}
__global__ void ugstats_kernel(const float* __restrict__ ug,
                               double* __restrict__ S1, double* __restrict__ S2)
{
    int c = threadIdx.x;
    double s1 = 0.0, s2 = 0.0;
    for (int g = 0; g < GRAPHS; g++) {
        double v = (double)ug[g * HID + c];
        s1 += v; s2 += v * v;
    }
    S1[HID + c] = s1;
    S2[HID + c] = s2;
}

// ---------------- fold BN into final linear ----------------------------------
__global__ void prep_kernel(const double* __restrict__ S1, const double* __restrict__ S2,
                            const float* __restrict__ gamma, const float* __restrict__ beta,
                            const float* __restrict__ Wf, const float* __restrict__ bf,
                            float* __restrict__ weff, float* __restrict__ beff)
{
    __shared__ float r0[256], r1[256];
    int c = threadIdx.x;
    double div  = (c < HID) ? (double)N_NODES : (double)GRAPHS;
    double mean = S1[c] / div;
    double var  = S2[c] / div - mean * mean;
    float  s     = gamma[c] * rsqrtf((float)var + 1e-5f);
    float  shift = beta[c] - (float)mean * s;
    float  w0 = Wf[c * 2 + 0], w1 = Wf[c * 2 + 1];
    weff[c * 2 + 0] = s * w0;
    weff[c * 2 + 1] = s * w1;
    r0[c] = shift * w0;
    r1[c] = shift * w1;
    __syncthreads();
    for (int st = 128; st > 0; st >>= 1) {
        if (c < st) { r0[c] += r0[c + st]; r1[c] += r1[c + st]; }
        __syncthreads();
    }
    if (c == 0) { beff[0] = bf[0] + r0[0]; beff[1] = bf[1] + r1[0]; }
}

// ---------------- final: out[n] = [x_n | ug_g] @ Weff + beff -----------------
__global__ __launch_bounds__(256) void final_kernel(
    const __nv_bfloat16* __restrict__ xh, const __nv_bfloat16* __restrict__ xl,
    const float* __restrict__ ug,
    const float* __restrict__ weff, const float* __restrict__ beff,
    float* __restrict__ out)
{
    __shared__ float wsh[512];
    __shared__ float ush[HID];
    __shared__ float bsh[2];
    int tid = threadIdx.x;
    int n0  = blockIdx.x * 256;
    wsh[tid]       = weff[tid];
    wsh[tid + 256] = weff[tid + 256];
    if (tid < 2)   bsh[tid] = beff[tid];
    int g = n0 >> 10;
    if (tid < HID) ush[tid] = ug[g * HID + tid];
    __syncthreads();

    int n = n0 + tid;
    float a0 = bsh[0], a1 = bsh[1];
    const __nv_bfloat162* hr = (const __nv_bfloat162*)(xh + (size_t)n * HID);
    const __nv_bfloat162* lr = (const __nv_bfloat162*)(xl + (size_t)n * HID);
#pragma unroll
    for (int c2 = 0; c2 < 64; c2++) {
        __nv_bfloat162 hv = hr[c2];
        __nv_bfloat162 lv = lr[c2];
        float v0 = __bfloat162float(hv.x) + __bfloat162float(lv.x);
        float v1 = __bfloat162float(hv.y) + __bfloat162float(lv.y);
        int c = 2 * c2;
        a0 += v0 * wsh[2*c + 0] + v1 * wsh[2*c + 2];
        a1 += v0 * wsh[2*c + 1] + v1 * wsh[2*c + 3];
    }
#pragma unroll 8
    for (int c = 0; c < HID; c++) {
        float uv = ush[c];
        a0 += uv * wsh[2 * (HID + c) + 0];
        a1 += uv * wsh[2 * (HID + c) + 1];
    }
    out[n * 2 + 0] = a0;
    out[n * 2 + 1] = a1;
}

// ---------------- host orchestration ----------------------------------------
extern "C" void kernel_launch(void* const* d_in, const int* in_sizes, int n_in,
                              void* d_out, int out_size)
{
    const float* x_in    = (const float*)d_in[0];
    const int*   ei      = (const int*)  d_in[1];
    const float* W_proj  = (const float*)d_in[3];
    const float* b_proj  = (const float*)d_in[4];
    const float* W_lay   = (const float*)d_in[5];
    const float* b_lay   = (const float*)d_in[6];
    const float* W_aggr  = (const float*)d_in[7];
    const float* b_aggr  = (const float*)d_in[8];
    const float* gamma   = (const float*)d_in[9];
    const float* beta    = (const float*)d_in[10];
    const float* W_final = (const float*)d_in[11];
    const float* b_final = (const float*)d_in[12];
    float* out = (float*)d_out;

    const int M = in_sizes[0] / IN_DIM;     // 65536
    const int E = in_sizes[1] / 2;          // 524288

    float *pxi, *pui, *pu, *pug, *pweff, *pbeff;
    __nv_bfloat16 *pxh, *pxl, *pinh, *pinl, *pwh, *pwl;
    double *ps1, *ps2;
    int *pdeg, *prows, *pcur, *pssrc;
    cudaGetSymbolAddress((void**)&pxh,   g_xh);
    cudaGetSymbolAddress((void**)&pxl,   g_xl);
    cudaGetSymbolAddress((void**)&pinh,  g_inh);
    cudaGetSymbolAddress((void**)&pinl,  g_inl);
    cudaGetSymbolAddress((void**)&pwh,   g_wh);
    cudaGetSymbolAddress((void**)&pwl,   g_wl);
    cudaGetSymbolAddress((void**)&pxi,   g_xi);
    cudaGetSymbolAddress((void**)&pui,   g_ui);
    cudaGetSymbolAddress((void**)&pu,    g_u);
    cudaGetSymbolAddress((void**)&pug,   g_ug);
    cudaGetSymbolAddress((void**)&ps1,   g_S1);
    cudaGetSymbolAddress((void**)&ps2,   g_S2);
    cudaGetSymbolAddress((void**)&pweff, g_weff);
    cudaGetSymbolAddress((void**)&pbeff, g_beff);
    cudaGetSymbolAddress((void**)&pdeg,  g_deg);
    cudaGetSymbolAddress((void**)&prows, g_rows);
    cudaGetSymbolAddress((void**)&pcur,  g_cur);
    cudaGetSymbolAddress((void**)&pssrc, g_ssrc);

    cudaFuncSetAttribute(gemm_mma_kernel,
                         cudaFuncAttributeMaxDynamicSharedMemorySize, SMEM_MM);

    // 1: weight pre-conversion   2: input split   3: CSR zero
    wconv_kernel<<<(W_TOTAL + 255) / 256, 256>>>(W_proj, W_lay, W_aggr, pwh, pwl);
    split_kernel<<<(M * IN_DIM / 4 + 255) / 256, 256>>>(x_in, pinh, pinl, M * IN_DIM / 4);
    zero_int_kernel<<<(M + 1023) / 1024, 1024>>>(pdeg, M);
    // 4: projection GEMM (the launch ncu captures) — bf16 hi/lo output only
    gemm_mma_kernel<<<512, 256, SMEM_MM>>>(pinh, pinl, pwh + OFF_PROJ, pwl + OFF_PROJ,
                                           b_proj, b_proj, nullptr, nullptr,
                                           pxh, pxl, IN_DIM, 1);
    // CSR build continues
    hist_kernel<<<(E + 255) / 256, 256>>>(ei, pdeg, E);
    scan_kernel<<<1, 1024>>>(pdeg, prows, pcur);
    fill_kernel<<<(E + 255) / 256, 256>>>(ei, pcur, pssrc, E);

    for (int l = 0; l < LAYERS; l++) {
        // one dual launch: blocks 0-511 -> xi (W_lay), 512-1023 -> ui (W_aggr)
        gemm_mma_kernel<<<1024, 256, SMEM_MM>>>(pxh, pxl, pwh + OFF_L(l), pwl + OFF_L(l),
                                                b_lay + l * HID, b_aggr + l * HID,
                                                pxi, pui, nullptr, nullptr, HID, 0);
        agg_fuse_kernel<<<M / 8, 256>>>(pui, prows, pssrc, pxi, pu, pxh, pxl,
                                        l == LAYERS - 1 ? 1 : 0);
    }

    graph_reduce_kernel<<<GRAPHS, HID>>>(pu, pug);
    zero_stats_kernel<<<1, 256>>>(ps1, ps2);
    xstats_kernel<<<M / 128, 64>>>(pxh, pxl, ps1, ps2);
    ugstats_kernel<<<1, HID>>>(pug, ps1, ps2);
    prep_kernel<<<1, 256>>>(ps1, ps2, gamma, beta, W_final, b_final, pweff, pbeff);
    final_kernel<<<M / 256, 256>>>(pxh, pxl, pug, pweff, pbeff, out);

    (void)n_in; (void)out_size;
}